// round 1
// baseline (speedup 1.0000x reference)
#include <cuda_runtime.h>
#include <cuda_bf16.h>
#include <cstdint>

// ============================================================================
// EncoderLayer: x -> MHA(+resid,LN) -> FFN(+resid,LN)
// B=4, S=2048, D=1024, H=16, dk=64, FF=4096.  All GEMMs via tf32 mma.sync.
// ============================================================================

namespace enc {

constexpr int Bn   = 4;
constexpr int Sn   = 2048;
constexpr int Dn   = 1024;
constexpr int Hn   = 16;
constexpr int DKn  = 64;
constexpr int DFFn = 4096;
constexpr int Mn   = Bn * Sn;  // 8192 rows of the token stream

// Scratch (device globals; no cudaMalloc allowed)
__device__ float g_q [Mn * Dn];
__device__ float g_k [Mn * Dn];
__device__ float g_v [Mn * Dn];
__device__ float g_o [Mn * Dn];   // attention output (concat heads)
__device__ float g_r [Mn * Dn];   // pre-LN residual sum (reused twice)
__device__ float g_x1[Mn * Dn];   // output of first LN
__device__ float g_h [Mn * DFFn]; // FFN hidden

__device__ __forceinline__ uint32_t f2tf(float f) {
    uint32_t r;
    asm("cvt.rna.tf32.f32 %0, %1;" : "=r"(r) : "f"(f));
    return r;
}

__device__ __forceinline__ void mma_tf32(float c[4],
    uint32_t a0, uint32_t a1, uint32_t a2, uint32_t a3,
    uint32_t b0, uint32_t b1)
{
    asm volatile(
        "mma.sync.aligned.m16n8k8.row.col.f32.tf32.tf32.f32 "
        "{%0,%1,%2,%3}, {%4,%5,%6,%7}, {%8,%9}, {%0,%1,%2,%3};"
        : "+f"(c[0]), "+f"(c[1]), "+f"(c[2]), "+f"(c[3])
        : "r"(a0), "r"(a1), "r"(a2), "r"(a3), "r"(b0), "r"(b1));
}

// ============================================================================
// GEMM: C[M,N] = A[M,K] @ W[N,K]^T + bias[N]  (+ resid[M,N]) (+ relu)
// BM=BN=128, BK=32. 256 threads = 8 warps in 2x4 grid, warp tile 64x32.
// ============================================================================
template<bool RELU, bool RESID>
__global__ __launch_bounds__(256)
void gemm_kernel(const float* __restrict__ A, const float* __restrict__ W,
                 const float* __restrict__ bias, const float* __restrict__ resid,
                 float* __restrict__ C, int M, int N, int K)
{
    constexpr int BM = 128, BN = 128, BK = 32, LDS_ = BK + 4;  // pad: frag LDS bank==lane
    __shared__ float As[BM * LDS_];
    __shared__ float Bs[BN * LDS_];

    const int bm = blockIdx.y * BM;
    const int bn = blockIdx.x * BN;
    const int tid  = threadIdx.x;
    const int warp = tid >> 5, lane = tid & 31;
    const int wm = (warp >> 2) * 64;   // warp row origin in tile
    const int wn = (warp & 3) * 32;    // warp col origin in tile
    const int g = lane >> 2, t = lane & 3;

    float acc[4][4][4];
    #pragma unroll
    for (int mf = 0; mf < 4; mf++)
        #pragma unroll
        for (int nf = 0; nf < 4; nf++)
            #pragma unroll
            for (int e = 0; e < 4; e++) acc[mf][nf][e] = 0.0f;

    // global->reg->smem staging: each thread owns 4 float4 of A and 4 of B
    const int lr  = tid >> 3;        // row stride 32 per step? no: idx mapping below
    (void)lr;
    int rowA[4], colA[4];
    #pragma unroll
    for (int i = 0; i < 4; i++) {
        int idx = tid + i * 256;     // 0..1023 over 128 rows x 8 float4
        rowA[i] = idx >> 3;
        colA[i] = (idx & 7) * 4;
    }
    const float* Ap = A + (size_t)bm * K;
    const float* Wp = W + (size_t)bn * K;

    float4 ra[4], rb[4];
    #pragma unroll
    for (int i = 0; i < 4; i++) {
        ra[i] = *(const float4*)(Ap + (size_t)rowA[i] * K + colA[i]);
        rb[i] = *(const float4*)(Wp + (size_t)rowA[i] * K + colA[i]);
    }

    const int T = K / BK;
    for (int kt = 0; kt < T; kt++) {
        #pragma unroll
        for (int i = 0; i < 4; i++) {
            *(float4*)(&As[rowA[i] * LDS_ + colA[i]]) = ra[i];
            *(float4*)(&Bs[rowA[i] * LDS_ + colA[i]]) = rb[i];
        }
        __syncthreads();

        if (kt + 1 < T) {
            const int k0 = (kt + 1) * BK;
            #pragma unroll
            for (int i = 0; i < 4; i++) {
                ra[i] = *(const float4*)(Ap + (size_t)rowA[i] * K + k0 + colA[i]);
                rb[i] = *(const float4*)(Wp + (size_t)rowA[i] * K + k0 + colA[i]);
            }
        }

        #pragma unroll
        for (int ks = 0; ks < 4; ks++) {
            uint32_t af[4][4], bf[4][2];
            #pragma unroll
            for (int mf = 0; mf < 4; mf++) {
                const int r0 = (wm + mf * 16 + g) * LDS_;
                const int r1 = (wm + mf * 16 + g + 8) * LDS_;
                const int c  = ks * 8 + t;
                af[mf][0] = f2tf(As[r0 + c]);
                af[mf][1] = f2tf(As[r1 + c]);
                af[mf][2] = f2tf(As[r0 + c + 4]);
                af[mf][3] = f2tf(As[r1 + c + 4]);
            }
            #pragma unroll
            for (int nf = 0; nf < 4; nf++) {
                const int nr = (wn + nf * 8 + g) * LDS_;
                const int c  = ks * 8 + t;
                bf[nf][0] = f2tf(Bs[nr + c]);
                bf[nf][1] = f2tf(Bs[nr + c + 4]);
            }
            #pragma unroll
            for (int mf = 0; mf < 4; mf++)
                #pragma unroll
                for (int nf = 0; nf < 4; nf++)
                    mma_tf32(acc[mf][nf], af[mf][0], af[mf][1], af[mf][2], af[mf][3],
                             bf[nf][0], bf[nf][1]);
        }
        __syncthreads();
    }

    // epilogue
    #pragma unroll
    for (int mf = 0; mf < 4; mf++) {
        const int row0 = bm + wm + mf * 16 + g;
        #pragma unroll
        for (int nf = 0; nf < 4; nf++) {
            const int col = bn + wn + nf * 8 + 2 * t;
            const float b0 = bias[col], b1 = bias[col + 1];
            float v0 = acc[mf][nf][0] + b0;
            float v1 = acc[mf][nf][1] + b1;
            float v2 = acc[mf][nf][2] + b0;
            float v3 = acc[mf][nf][3] + b1;
            if (RESID) {
                const float* r0p = resid + (size_t)row0 * N + col;
                const float* r1p = resid + (size_t)(row0 + 8) * N + col;
                v0 += r0p[0]; v1 += r0p[1];
                v2 += r1p[0]; v3 += r1p[1];
            }
            if (RELU) {
                v0 = fmaxf(v0, 0.0f); v1 = fmaxf(v1, 0.0f);
                v2 = fmaxf(v2, 0.0f); v3 = fmaxf(v3, 0.0f);
            }
            *(float2*)(&C[(size_t)row0 * N + col])       = make_float2(v0, v1);
            *(float2*)(&C[(size_t)(row0 + 8) * N + col]) = make_float2(v2, v3);
        }
    }
}

// ============================================================================
// Flash attention. One CTA per (q-tile of 64, head, batch). 128 threads.
// Tiles of 64 keys; online softmax; P round-trips through warp-private smem.
// ============================================================================
constexpr int FLASH_LD   = 68;                       // 64 + 4 pad
constexpr int FLASH_SMEM = (4 * 64 * FLASH_LD + 64) * 4;  // Qs,Ks,Vs,Ps + mask

__global__ __launch_bounds__(128)
void flash_kernel(const float* __restrict__ Q, const float* __restrict__ Km,
                  const float* __restrict__ V, const float* __restrict__ mask,
                  float* __restrict__ O)
{
    extern __shared__ float sm[];
    float* Qs = sm;
    float* Ks = sm + 64 * FLASH_LD;
    float* Vs = sm + 2 * 64 * FLASH_LD;
    float* Ps = sm + 3 * 64 * FLASH_LD;
    float* Ms = sm + 4 * 64 * FLASH_LD;

    const int qt = blockIdx.x, h = blockIdx.y, b = blockIdx.z;
    const int tid = threadIdx.x;
    const int warp = tid >> 5, lane = tid & 31;
    const int g = lane >> 2, t = lane & 3;
    constexpr float SCALE = 0.125f;  // 1/sqrt(64)

    const float* Qb = Q + (size_t)(b * Sn + qt * 64) * Dn + h * DKn;

    // load Q tile (64 x 64)
    for (int i = tid; i < 64 * 16; i += 128) {
        const int r = i >> 4, c4 = (i & 15) * 4;
        *(float4*)(&Qs[r * FLASH_LD + c4]) = *(const float4*)(Qb + (size_t)r * Dn + c4);
    }

    float m0 = -1e30f, m1 = -1e30f, l0 = 0.0f, l1 = 0.0f;
    float o[8][4];
    #pragma unroll
    for (int nf = 0; nf < 8; nf++)
        #pragma unroll
        for (int e = 0; e < 4; e++) o[nf][e] = 0.0f;

    const float* Kb0 = Km + (size_t)(b * Sn) * Dn + h * DKn;
    const float* Vb0 = V  + (size_t)(b * Sn) * Dn + h * DKn;
    const int prow0 = (warp * 16 + g) * FLASH_LD;
    const int prow1 = (warp * 16 + g + 8) * FLASH_LD;

    for (int kt = 0; kt < Sn / 64; kt++) {
        const float* Kb = Kb0 + (size_t)kt * 64 * Dn;
        const float* Vb = Vb0 + (size_t)kt * 64 * Dn;
        for (int i = tid; i < 64 * 16; i += 128) {
            const int r = i >> 4, c4 = (i & 15) * 4;
            *(float4*)(&Ks[r * FLASH_LD + c4]) = *(const float4*)(Kb + (size_t)r * Dn + c4);
            *(float4*)(&Vs[r * FLASH_LD + c4]) = *(const float4*)(Vb + (size_t)r * Dn + c4);
        }
        if (tid < 64) Ms[tid] = mask[b * Sn + kt * 64 + tid];
        __syncthreads();

        // S = Q K^T  (64 x 64), warp owns 16 q-rows
        float s[8][4];
        #pragma unroll
        for (int nf = 0; nf < 8; nf++)
            #pragma unroll
            for (int e = 0; e < 4; e++) s[nf][e] = 0.0f;

        #pragma unroll
        for (int ks = 0; ks < 8; ks++) {
            const int c = ks * 8 + t;
            const uint32_t a0 = f2tf(Qs[prow0 + c]);
            const uint32_t a1 = f2tf(Qs[prow1 + c]);
            const uint32_t a2 = f2tf(Qs[prow0 + c + 4]);
            const uint32_t a3 = f2tf(Qs[prow1 + c + 4]);
            #pragma unroll
            for (int nf = 0; nf < 8; nf++) {
                const int nr = (nf * 8 + g) * FLASH_LD;
                const uint32_t b0 = f2tf(Ks[nr + c]);
                const uint32_t b1 = f2tf(Ks[nr + c + 4]);
                mma_tf32(s[nf], a0, a1, a2, a3, b0, b1);
            }
        }

        // scale + mask + row max
        float rmax0 = -1e30f, rmax1 = -1e30f;
        #pragma unroll
        for (int nf = 0; nf < 8; nf++) {
            const float mk0 = Ms[nf * 8 + 2 * t];
            const float mk1 = Ms[nf * 8 + 2 * t + 1];
            s[nf][0] = s[nf][0] * SCALE + mk0;
            s[nf][1] = s[nf][1] * SCALE + mk1;
            s[nf][2] = s[nf][2] * SCALE + mk0;
            s[nf][3] = s[nf][3] * SCALE + mk1;
            rmax0 = fmaxf(rmax0, fmaxf(s[nf][0], s[nf][1]));
            rmax1 = fmaxf(rmax1, fmaxf(s[nf][2], s[nf][3]));
        }
        rmax0 = fmaxf(rmax0, __shfl_xor_sync(0xffffffffu, rmax0, 1));
        rmax0 = fmaxf(rmax0, __shfl_xor_sync(0xffffffffu, rmax0, 2));
        rmax1 = fmaxf(rmax1, __shfl_xor_sync(0xffffffffu, rmax1, 1));
        rmax1 = fmaxf(rmax1, __shfl_xor_sync(0xffffffffu, rmax1, 2));

        const float mn0 = fmaxf(m0, rmax0), mn1 = fmaxf(m1, rmax1);
        const float sc0 = __expf(m0 - mn0), sc1 = __expf(m1 - mn1);

        float rs0 = 0.0f, rs1 = 0.0f;
        #pragma unroll
        for (int nf = 0; nf < 8; nf++) {
            s[nf][0] = __expf(s[nf][0] - mn0);
            s[nf][1] = __expf(s[nf][1] - mn0);
            s[nf][2] = __expf(s[nf][2] - mn1);
            s[nf][3] = __expf(s[nf][3] - mn1);
            rs0 += s[nf][0] + s[nf][1];
            rs1 += s[nf][2] + s[nf][3];
        }
        rs0 += __shfl_xor_sync(0xffffffffu, rs0, 1);
        rs0 += __shfl_xor_sync(0xffffffffu, rs0, 2);
        rs1 += __shfl_xor_sync(0xffffffffu, rs1, 1);
        rs1 += __shfl_xor_sync(0xffffffffu, rs1, 2);

        l0 = l0 * sc0 + rs0;
        l1 = l1 * sc1 + rs1;
        m0 = mn0; m1 = mn1;

        #pragma unroll
        for (int nf = 0; nf < 8; nf++) {
            o[nf][0] *= sc0; o[nf][1] *= sc0;
            o[nf][2] *= sc1; o[nf][3] *= sc1;
        }

        // P -> warp-private smem rows (re-layout C-frag -> A-frag)
        #pragma unroll
        for (int nf = 0; nf < 8; nf++) {
            const int c = nf * 8 + 2 * t;
            Ps[prow0 + c]     = s[nf][0];
            Ps[prow0 + c + 1] = s[nf][1];
            Ps[prow1 + c]     = s[nf][2];
            Ps[prow1 + c + 1] = s[nf][3];
        }
        __syncwarp();

        // O += P V  (contraction over 64 keys)
        #pragma unroll
        for (int ks = 0; ks < 8; ks++) {
            const int c = ks * 8 + t;
            const uint32_t a0 = f2tf(Ps[prow0 + c]);
            const uint32_t a1 = f2tf(Ps[prow1 + c]);
            const uint32_t a2 = f2tf(Ps[prow0 + c + 4]);
            const uint32_t a3 = f2tf(Ps[prow1 + c + 4]);
            #pragma unroll
            for (int nf = 0; nf < 8; nf++) {
                const uint32_t b0 = f2tf(Vs[(c)     * FLASH_LD + nf * 8 + g]);
                const uint32_t b1 = f2tf(Vs[(c + 4) * FLASH_LD + nf * 8 + g]);
                mma_tf32(o[nf], a0, a1, a2, a3, b0, b1);
            }
        }
        __syncthreads();
    }

    const float inv0 = 1.0f / l0, inv1 = 1.0f / l1;
    const int orow0 = b * Sn + qt * 64 + warp * 16 + g;
    #pragma unroll
    for (int nf = 0; nf < 8; nf++) {
        const int col = h * DKn + nf * 8 + 2 * t;
        *(float2*)(&O[(size_t)orow0 * Dn + col]) =
            make_float2(o[nf][0] * inv0, o[nf][1] * inv0);
        *(float2*)(&O[(size_t)(orow0 + 8) * Dn + col]) =
            make_float2(o[nf][2] * inv1, o[nf][3] * inv1);
    }
}

// ============================================================================
// LayerNorm over rows of 1024. One block (256 thr) per row, two-pass.
// ============================================================================
__global__ __launch_bounds__(256)
void layernorm_kernel(const float* __restrict__ in, const float* __restrict__ gamma,
                      const float* __restrict__ beta, float* __restrict__ out)
{
    __shared__ float sb[9];
    const int row = blockIdx.x;
    const int tid = threadIdx.x;
    const float4 xv = *(const float4*)(in + (size_t)row * Dn + tid * 4);

    float ssum = xv.x + xv.y + xv.z + xv.w;
    #pragma unroll
    for (int off = 16; off; off >>= 1) ssum += __shfl_xor_sync(0xffffffffu, ssum, off);
    if ((tid & 31) == 0) sb[tid >> 5] = ssum;
    __syncthreads();
    if (tid == 0) {
        float s = 0.0f;
        #pragma unroll
        for (int i = 0; i < 8; i++) s += sb[i];
        sb[8] = s;
    }
    __syncthreads();
    const float mu = sb[8] * (1.0f / Dn);

    const float d0 = xv.x - mu, d1 = xv.y - mu, d2 = xv.z - mu, d3 = xv.w - mu;
    float sq = d0 * d0 + d1 * d1 + d2 * d2 + d3 * d3;
    __syncthreads();  // everyone has read sb[8]
    #pragma unroll
    for (int off = 16; off; off >>= 1) sq += __shfl_xor_sync(0xffffffffu, sq, off);
    if ((tid & 31) == 0) sb[tid >> 5] = sq;
    __syncthreads();
    if (tid == 0) {
        float s = 0.0f;
        #pragma unroll
        for (int i = 0; i < 8; i++) s += sb[i];
        sb[8] = s;
    }
    __syncthreads();
    const float inv = rsqrtf(sb[8] * (1.0f / Dn) + 1e-5f);

    const float4 gv = *(const float4*)(gamma + tid * 4);
    const float4 bv = *(const float4*)(beta + tid * 4);
    float4 ov;
    ov.x = d0 * inv * gv.x + bv.x;
    ov.y = d1 * inv * gv.y + bv.y;
    ov.z = d2 * inv * gv.z + bv.z;
    ov.w = d3 * inv * gv.w + bv.w;
    *(float4*)(out + (size_t)row * Dn + tid * 4) = ov;
}

} // namespace enc

// ============================================================================
// kernel_launch
// ============================================================================
extern "C" void kernel_launch(void* const* d_in, const int* in_sizes, int n_in,
                              void* d_out, int out_size)
{
    using namespace enc;
    (void)in_sizes; (void)n_in; (void)out_size;

    const float* x    = (const float*)d_in[0];
    const float* mask = (const float*)d_in[1];
    const float* Wq   = (const float*)d_in[2];
    const float* bq   = (const float*)d_in[3];
    const float* Wk   = (const float*)d_in[4];
    const float* bk   = (const float*)d_in[5];
    const float* Wv   = (const float*)d_in[6];
    const float* bv   = (const float*)d_in[7];
    const float* Wo   = (const float*)d_in[8];
    const float* bo   = (const float*)d_in[9];
    const float* W1   = (const float*)d_in[10];
    const float* b1   = (const float*)d_in[11];
    const float* W2   = (const float*)d_in[12];
    const float* b2   = (const float*)d_in[13];
    const float* g1   = (const float*)d_in[14];
    const float* be1  = (const float*)d_in[15];
    const float* g2   = (const float*)d_in[16];
    const float* be2  = (const float*)d_in[17];
    float* out = (float*)d_out;

    float *q, *k, *v, *o, *r, *x1, *h;
    cudaGetSymbolAddress((void**)&q,  g_q);
    cudaGetSymbolAddress((void**)&k,  g_k);
    cudaGetSymbolAddress((void**)&v,  g_v);
    cudaGetSymbolAddress((void**)&o,  g_o);
    cudaGetSymbolAddress((void**)&r,  g_r);
    cudaGetSymbolAddress((void**)&x1, g_x1);
    cudaGetSymbolAddress((void**)&h,  g_h);

    cudaFuncSetAttribute(flash_kernel,
                         cudaFuncAttributeMaxDynamicSharedMemorySize, FLASH_SMEM);

    const dim3 gD(Dn / 128, Mn / 128);    // 8 x 64
    const dim3 gF(DFFn / 128, Mn / 128);  // 32 x 64

    // QKV projections
    gemm_kernel<false, false><<<gD, 256>>>(x, Wq, bq, nullptr, q, Mn, Dn, Dn);
    gemm_kernel<false, false><<<gD, 256>>>(x, Wk, bk, nullptr, k, Mn, Dn, Dn);
    gemm_kernel<false, false><<<gD, 256>>>(x, Wv, bv, nullptr, v, Mn, Dn, Dn);

    // attention
    flash_kernel<<<dim3(Sn / 64, Hn, Bn), 128, FLASH_SMEM>>>(q, k, v, mask, o);

    // O projection + residual, then LN1
    gemm_kernel<false, true><<<gD, 256>>>(o, Wo, bo, x, r, Mn, Dn, Dn);
    layernorm_kernel<<<Mn, 256>>>(r, g1, be1, x1);

    // FFN
    gemm_kernel<true, false><<<gF, 256>>>(x1, W1, b1, nullptr, h, Mn, DFFn, Dn);
    gemm_kernel<false, true><<<gD, 256>>>(h, W2, b2, x1, r, Mn, Dn, DFFn);
    layernorm_kernel<<<Mn, 256>>>(r, g2, be2, out);
}

// round 3
// speedup vs baseline: 1.1340x; 1.1340x over previous
#include <cuda_runtime.h>
#include <cuda_bf16.h>
#include <cstdint>

// ============================================================================
// EncoderLayer: x -> MHA(+resid,LN) -> FFN(+resid,LN)
// B=4, S=2048, D=1024, H=16, dk=64, FF=4096.  All GEMMs via tf32 mma.sync.
// R3 (= R2 resubmit; infra failure last round):
//   - cp.async 3-stage GEMM pipeline, fused QKV launch
//   - flash with Q-in-regs, convert-at-staging (tf32 in smem), Ps overlays Qs
// ============================================================================

namespace enc {

constexpr int Bn   = 4;
constexpr int Sn   = 2048;
constexpr int Dn   = 1024;
constexpr int Hn   = 16;
constexpr int DKn  = 64;
constexpr int DFFn = 4096;
constexpr int Mn   = Bn * Sn;

// Scratch (device globals; no cudaMalloc allowed)
__device__ float g_q [Mn * Dn];
__device__ float g_k [Mn * Dn];
__device__ float g_v [Mn * Dn];
__device__ float g_o [Mn * Dn];
__device__ float g_r [Mn * Dn];
__device__ float g_x1[Mn * Dn];
__device__ float g_h [Mn * DFFn];

__device__ __forceinline__ uint32_t f2tf(float f) {
    uint32_t r;
    asm("cvt.rna.tf32.f32 %0, %1;" : "=r"(r) : "f"(f));
    return r;
}

__device__ __forceinline__ void mma_tf32(float c[4],
    uint32_t a0, uint32_t a1, uint32_t a2, uint32_t a3,
    uint32_t b0, uint32_t b1)
{
    asm volatile(
        "mma.sync.aligned.m16n8k8.row.col.f32.tf32.tf32.f32 "
        "{%0,%1,%2,%3}, {%4,%5,%6,%7}, {%8,%9}, {%0,%1,%2,%3};"
        : "+f"(c[0]), "+f"(c[1]), "+f"(c[2]), "+f"(c[3])
        : "r"(a0), "r"(a1), "r"(a2), "r"(a3), "r"(b0), "r"(b1));
}

__device__ __forceinline__ void cp16(float* smem_dst, const float* gsrc) {
    uint32_t sa = (uint32_t)__cvta_generic_to_shared(smem_dst);
    asm volatile("cp.async.cg.shared.global [%0], [%1], 16;\n"
                 :: "r"(sa), "l"(gsrc));
}
__device__ __forceinline__ void cp_commit() {
    asm volatile("cp.async.commit_group;\n");
}
template<int N>
__device__ __forceinline__ void cp_wait() {
    asm volatile("cp.async.wait_group %0;\n" :: "n"(N));
}

// ============================================================================
// GEMM body: C tile = A[BM,K] @ W[BN,K]^T + bias (+resid)(+relu)
// BM=BN=128, BK=32, 3-stage cp.async pipeline, 256 thr (2x4 warps, 64x32).
// ============================================================================
constexpr int GEMM_STAGES = 3;
constexpr int GEMM_LDS    = 36;  // 32 + 4 pad: frag LDS bank == lane, 16B aligned
constexpr int GEMM_STAGE_F = 128 * GEMM_LDS;
constexpr int GEMM_SMEM = GEMM_STAGES * 2 * GEMM_STAGE_F * 4;  // bytes

template<bool RELU, bool RESID>
__device__ __forceinline__ void gemm_body(
    const float* __restrict__ A, const float* __restrict__ W,
    const float* __restrict__ bias, const float* __restrict__ resid,
    float* __restrict__ C, int N, int K, int bm, int bn, float* smem)
{
    constexpr int BK = 32;
    float* As = smem;
    float* Bs = smem + GEMM_STAGES * GEMM_STAGE_F;

    const int tid  = threadIdx.x;
    const int warp = tid >> 5, lane = tid & 31;
    const int wm = (warp >> 2) * 64;
    const int wn = (warp & 3) * 32;
    const int g = lane >> 2, t = lane & 3;

    int rowS[4], colS[4];
    #pragma unroll
    for (int i = 0; i < 4; i++) {
        int idx = tid + i * 256;
        rowS[i] = idx >> 3;
        colS[i] = (idx & 7) * 4;
    }
    const float* Ap = A + (size_t)bm * K;
    const float* Wp = W + (size_t)bn * K;

    float acc[4][4][4];
    #pragma unroll
    for (int mf = 0; mf < 4; mf++)
        #pragma unroll
        for (int nf = 0; nf < 4; nf++)
            #pragma unroll
            for (int e = 0; e < 4; e++) acc[mf][nf][e] = 0.0f;

    const int T = K / BK;

    // prologue: stages 0..STAGES-2
    #pragma unroll
    for (int s = 0; s < GEMM_STAGES - 1; s++) {
        float* as = As + s * GEMM_STAGE_F;
        float* bs = Bs + s * GEMM_STAGE_F;
        const int k0 = s * BK;
        #pragma unroll
        for (int i = 0; i < 4; i++) {
            cp16(as + rowS[i] * GEMM_LDS + colS[i], Ap + (size_t)rowS[i] * K + k0 + colS[i]);
            cp16(bs + rowS[i] * GEMM_LDS + colS[i], Wp + (size_t)rowS[i] * K + k0 + colS[i]);
        }
        cp_commit();
    }

    for (int kt = 0; kt < T; kt++) {
        cp_wait<GEMM_STAGES - 2>();
        __syncthreads();

        // issue loads for stage kt+STAGES-1 (overwrites stage computed at kt-1)
        if (kt + GEMM_STAGES - 1 < T) {
            const int s = (kt + GEMM_STAGES - 1) % GEMM_STAGES;
            float* as = As + s * GEMM_STAGE_F;
            float* bs = Bs + s * GEMM_STAGE_F;
            const int k0 = (kt + GEMM_STAGES - 1) * BK;
            #pragma unroll
            for (int i = 0; i < 4; i++) {
                cp16(as + rowS[i] * GEMM_LDS + colS[i], Ap + (size_t)rowS[i] * K + k0 + colS[i]);
                cp16(bs + rowS[i] * GEMM_LDS + colS[i], Wp + (size_t)rowS[i] * K + k0 + colS[i]);
            }
        }
        cp_commit();

        const float* as = As + (kt % GEMM_STAGES) * GEMM_STAGE_F;
        const float* bs = Bs + (kt % GEMM_STAGES) * GEMM_STAGE_F;

        #pragma unroll
        for (int ks = 0; ks < 4; ks++) {
            uint32_t af[4][4], bf[4][2];
            const int c = ks * 8 + t;
            #pragma unroll
            for (int mf = 0; mf < 4; mf++) {
                const int r0 = (wm + mf * 16 + g) * GEMM_LDS;
                const int r1 = r0 + 8 * GEMM_LDS;
                af[mf][0] = f2tf(as[r0 + c]);
                af[mf][1] = f2tf(as[r1 + c]);
                af[mf][2] = f2tf(as[r0 + c + 4]);
                af[mf][3] = f2tf(as[r1 + c + 4]);
            }
            #pragma unroll
            for (int nf = 0; nf < 4; nf++) {
                const int nr = (wn + nf * 8 + g) * GEMM_LDS;
                bf[nf][0] = f2tf(bs[nr + c]);
                bf[nf][1] = f2tf(bs[nr + c + 4]);
            }
            #pragma unroll
            for (int mf = 0; mf < 4; mf++)
                #pragma unroll
                for (int nf = 0; nf < 4; nf++)
                    mma_tf32(acc[mf][nf], af[mf][0], af[mf][1], af[mf][2], af[mf][3],
                             bf[nf][0], bf[nf][1]);
        }
    }

    // epilogue
    #pragma unroll
    for (int mf = 0; mf < 4; mf++) {
        const int row0 = bm + wm + mf * 16 + g;
        #pragma unroll
        for (int nf = 0; nf < 4; nf++) {
            const int col = bn + wn + nf * 8 + 2 * t;
            const float b0 = bias[col], b1 = bias[col + 1];
            float v0 = acc[mf][nf][0] + b0;
            float v1 = acc[mf][nf][1] + b1;
            float v2 = acc[mf][nf][2] + b0;
            float v3 = acc[mf][nf][3] + b1;
            if (RESID) {
                const float2 r0v = *(const float2*)(resid + (size_t)row0 * N + col);
                const float2 r1v = *(const float2*)(resid + (size_t)(row0 + 8) * N + col);
                v0 += r0v.x; v1 += r0v.y;
                v2 += r1v.x; v3 += r1v.y;
            }
            if (RELU) {
                v0 = fmaxf(v0, 0.0f); v1 = fmaxf(v1, 0.0f);
                v2 = fmaxf(v2, 0.0f); v3 = fmaxf(v3, 0.0f);
            }
            *(float2*)(&C[(size_t)row0 * N + col])       = make_float2(v0, v1);
            *(float2*)(&C[(size_t)(row0 + 8) * N + col]) = make_float2(v2, v3);
        }
    }
}

template<bool RELU, bool RESID>
__global__ __launch_bounds__(256)
void gemm_kernel(const float* __restrict__ A, const float* __restrict__ W,
                 const float* __restrict__ bias, const float* __restrict__ resid,
                 float* __restrict__ C, int N, int K)
{
    extern __shared__ float smem[];
    gemm_body<RELU, RESID>(A, W, bias, resid, C, N, K,
                           blockIdx.y * 128, blockIdx.x * 128, smem);
}

// Fused QKV: one launch, blockIdx.x in [0,24): sel = x/8 picks {q,k,v}
__global__ __launch_bounds__(256)
void gemm_qkv_kernel(const float* __restrict__ x,
                     const float* __restrict__ Wq, const float* __restrict__ bq,
                     const float* __restrict__ Wk, const float* __restrict__ bk,
                     const float* __restrict__ Wv, const float* __restrict__ bv,
                     float* __restrict__ q, float* __restrict__ k, float* __restrict__ v)
{
    extern __shared__ float smem[];
    const int sel = blockIdx.x >> 3;
    const int bx  = blockIdx.x & 7;
    const float* W = (sel == 0) ? Wq : (sel == 1) ? Wk : Wv;
    const float* b = (sel == 0) ? bq : (sel == 1) ? bk : bv;
    float*       C = (sel == 0) ? q  : (sel == 1) ? k  : v;
    gemm_body<false, false>(x, W, b, nullptr, C, Dn, Dn,
                            blockIdx.y * 128, bx * 128, smem);
}

// ============================================================================
// Flash attention. CTA = (64 q-rows, head, batch), 128 threads.
// Q fragments hoisted to registers (tf32, converted once). K/V/P stored in
// smem already converted to tf32. Ps overlays Qs.
// ============================================================================
constexpr int FLD = 68;                                 // 64 + 4 pad
constexpr int FLASH_SMEM = (3 * 64 * FLD + 64) * 4;     // Qs/Ps, Ks, Vs, mask

__global__ __launch_bounds__(128)
void flash_kernel(const float* __restrict__ Q, const float* __restrict__ Km,
                  const float* __restrict__ V, const float* __restrict__ mask,
                  float* __restrict__ O)
{
    extern __shared__ float sm[];
    float* Qs = sm;                    // reused as Ps after Q-frag extraction
    float* Ks = sm + 64 * FLD;
    float* Vs = sm + 2 * 64 * FLD;
    float* Ms = sm + 3 * 64 * FLD;

    const int qt = blockIdx.x, h = blockIdx.y, b = blockIdx.z;
    const int tid = threadIdx.x;
    const int warp = tid >> 5, lane = tid & 31;
    const int g = lane >> 2, t = lane & 3;
    constexpr float SCALE = 0.125f;

    const float* Qb = Q + (size_t)(b * Sn + qt * 64) * Dn + h * DKn;
    for (int i = tid; i < 64 * 16; i += 128) {
        const int r = i >> 4, c4 = (i & 15) * 4;
        *(float4*)(&Qs[r * FLD + c4]) = *(const float4*)(Qb + (size_t)r * Dn + c4);
    }
    __syncthreads();

    // Extract Q fragments to registers (tf32) — done once, reused 32 k-tiles
    const int prow0 = (warp * 16 + g) * FLD;
    const int prow1 = prow0 + 8 * FLD;
    uint32_t aq[8][4];
    #pragma unroll
    for (int ks = 0; ks < 8; ks++) {
        const int c = ks * 8 + t;
        aq[ks][0] = f2tf(Qs[prow0 + c]);
        aq[ks][1] = f2tf(Qs[prow1 + c]);
        aq[ks][2] = f2tf(Qs[prow0 + c + 4]);
        aq[ks][3] = f2tf(Qs[prow1 + c + 4]);
    }
    __syncthreads();
    float* Ps = Qs;

    float m0 = -1e30f, m1 = -1e30f, l0 = 0.0f, l1 = 0.0f;
    float o[8][4];
    #pragma unroll
    for (int nf = 0; nf < 8; nf++)
        #pragma unroll
        for (int e = 0; e < 4; e++) o[nf][e] = 0.0f;

    const float* Kb0 = Km + (size_t)(b * Sn) * Dn + h * DKn;
    const float* Vb0 = V  + (size_t)(b * Sn) * Dn + h * DKn;

    for (int kt = 0; kt < Sn / 64; kt++) {
        const float* Kb = Kb0 + (size_t)kt * 64 * Dn;
        const float* Vb = Vb0 + (size_t)kt * 64 * Dn;
        // stage K,V converted to tf32
        for (int i = tid; i < 64 * 16; i += 128) {
            const int r = i >> 4, c4 = (i & 15) * 4;
            float4 kv = *(const float4*)(Kb + (size_t)r * Dn + c4);
            float4 vv = *(const float4*)(Vb + (size_t)r * Dn + c4);
            uint4 ku, vu;
            ku.x = f2tf(kv.x); ku.y = f2tf(kv.y); ku.z = f2tf(kv.z); ku.w = f2tf(kv.w);
            vu.x = f2tf(vv.x); vu.y = f2tf(vv.y); vu.z = f2tf(vv.z); vu.w = f2tf(vv.w);
            *(uint4*)(&Ks[r * FLD + c4]) = ku;
            *(uint4*)(&Vs[r * FLD + c4]) = vu;
        }
        if (tid < 64) Ms[tid] = mask[b * Sn + kt * 64 + tid];
        __syncthreads();

        // S = Q K^T (warp owns 16 q-rows x 64 keys)
        float s[8][4];
        #pragma unroll
        for (int nf = 0; nf < 8; nf++)
            #pragma unroll
            for (int e = 0; e < 4; e++) s[nf][e] = 0.0f;

        #pragma unroll
        for (int ks = 0; ks < 8; ks++) {
            const int c = ks * 8 + t;
            #pragma unroll
            for (int nf = 0; nf < 8; nf++) {
                const int nr = (nf * 8 + g) * FLD;
                const uint32_t b0 = __float_as_uint(Ks[nr + c]);
                const uint32_t b1 = __float_as_uint(Ks[nr + c + 4]);
                mma_tf32(s[nf], aq[ks][0], aq[ks][1], aq[ks][2], aq[ks][3], b0, b1);
            }
        }

        // scale + mask + row max
        float rmax0 = -1e30f, rmax1 = -1e30f;
        #pragma unroll
        for (int nf = 0; nf < 8; nf++) {
            const float mk0 = Ms[nf * 8 + 2 * t];
            const float mk1 = Ms[nf * 8 + 2 * t + 1];
            s[nf][0] = s[nf][0] * SCALE + mk0;
            s[nf][1] = s[nf][1] * SCALE + mk1;
            s[nf][2] = s[nf][2] * SCALE + mk0;
            s[nf][3] = s[nf][3] * SCALE + mk1;
            rmax0 = fmaxf(rmax0, fmaxf(s[nf][0], s[nf][1]));
            rmax1 = fmaxf(rmax1, fmaxf(s[nf][2], s[nf][3]));
        }
        rmax0 = fmaxf(rmax0, __shfl_xor_sync(0xffffffffu, rmax0, 1));
        rmax0 = fmaxf(rmax0, __shfl_xor_sync(0xffffffffu, rmax0, 2));
        rmax1 = fmaxf(rmax1, __shfl_xor_sync(0xffffffffu, rmax1, 1));
        rmax1 = fmaxf(rmax1, __shfl_xor_sync(0xffffffffu, rmax1, 2));

        const float mn0 = fmaxf(m0, rmax0), mn1 = fmaxf(m1, rmax1);
        const float sc0 = __expf(m0 - mn0), sc1 = __expf(m1 - mn1);

        float rs0 = 0.0f, rs1 = 0.0f;
        #pragma unroll
        for (int nf = 0; nf < 8; nf++) {
            s[nf][0] = __expf(s[nf][0] - mn0);
            s[nf][1] = __expf(s[nf][1] - mn0);
            s[nf][2] = __expf(s[nf][2] - mn1);
            s[nf][3] = __expf(s[nf][3] - mn1);
            rs0 += s[nf][0] + s[nf][1];
            rs1 += s[nf][2] + s[nf][3];
        }
        rs0 += __shfl_xor_sync(0xffffffffu, rs0, 1);
        rs0 += __shfl_xor_sync(0xffffffffu, rs0, 2);
        rs1 += __shfl_xor_sync(0xffffffffu, rs1, 1);
        rs1 += __shfl_xor_sync(0xffffffffu, rs1, 2);

        l0 = l0 * sc0 + rs0;
        l1 = l1 * sc1 + rs1;
        m0 = mn0; m1 = mn1;

        #pragma unroll
        for (int nf = 0; nf < 8; nf++) {
            o[nf][0] *= sc0; o[nf][1] *= sc0;
            o[nf][2] *= sc1; o[nf][3] *= sc1;
        }

        // P -> warp-private smem rows (stored pre-converted to tf32)
        #pragma unroll
        for (int nf = 0; nf < 8; nf++) {
            const int c = nf * 8 + 2 * t;
            *(uint2*)(&Ps[prow0 + c]) = make_uint2(f2tf(s[nf][0]), f2tf(s[nf][1]));
            *(uint2*)(&Ps[prow1 + c]) = make_uint2(f2tf(s[nf][2]), f2tf(s[nf][3]));
        }
        __syncwarp();

        // O += P V
        #pragma unroll
        for (int ks = 0; ks < 8; ks++) {
            const int c = ks * 8 + t;
            const uint32_t a0 = __float_as_uint(Ps[prow0 + c]);
            const uint32_t a1 = __float_as_uint(Ps[prow1 + c]);
            const uint32_t a2 = __float_as_uint(Ps[prow0 + c + 4]);
            const uint32_t a3 = __float_as_uint(Ps[prow1 + c + 4]);
            #pragma unroll
            for (int nf = 0; nf < 8; nf++) {
                const uint32_t b0 = __float_as_uint(Vs[(c)     * FLD + nf * 8 + g]);
                const uint32_t b1 = __float_as_uint(Vs[(c + 4) * FLD + nf * 8 + g]);
                mma_tf32(o[nf], a0, a1, a2, a3, b0, b1);
            }
        }
        __syncthreads();
    }

    const float inv0 = 1.0f / l0, inv1 = 1.0f / l1;
    const int orow0 = b * Sn + qt * 64 + warp * 16 + g;
    #pragma unroll
    for (int nf = 0; nf < 8; nf++) {
        const int col = h * DKn + nf * 8 + 2 * t;
        *(float2*)(&O[(size_t)orow0 * Dn + col]) =
            make_float2(o[nf][0] * inv0, o[nf][1] * inv0);
        *(float2*)(&O[(size_t)(orow0 + 8) * Dn + col]) =
            make_float2(o[nf][2] * inv1, o[nf][3] * inv1);
    }
}

// ============================================================================
// LayerNorm over rows of 1024. One block (256 thr) per row, two-pass.
// ============================================================================
__global__ __launch_bounds__(256)
void layernorm_kernel(const float* __restrict__ in, const float* __restrict__ gamma,
                      const float* __restrict__ beta, float* __restrict__ out)
{
    __shared__ float sb[9];
    const int row = blockIdx.x;
    const int tid = threadIdx.x;
    const float4 xv = *(const float4*)(in + (size_t)row * Dn + tid * 4);

    float ssum = xv.x + xv.y + xv.z + xv.w;
    #pragma unroll
    for (int off = 16; off; off >>= 1) ssum += __shfl_xor_sync(0xffffffffu, ssum, off);
    if ((tid & 31) == 0) sb[tid >> 5] = ssum;
    __syncthreads();
    if (tid == 0) {
        float s = 0.0f;
        #pragma unroll
        for (int i = 0; i < 8; i++) s += sb[i];
        sb[8] = s;
    }
    __syncthreads();
    const float mu = sb[8] * (1.0f / Dn);

    const float d0 = xv.x - mu, d1 = xv.y - mu, d2 = xv.z - mu, d3 = xv.w - mu;
    float sq = d0 * d0 + d1 * d1 + d2 * d2 + d3 * d3;
    __syncthreads();
    #pragma unroll
    for (int off = 16; off; off >>= 1) sq += __shfl_xor_sync(0xffffffffu, sq, off);
    if ((tid & 31) == 0) sb[tid >> 5] = sq;
    __syncthreads();
    if (tid == 0) {
        float s = 0.0f;
        #pragma unroll
        for (int i = 0; i < 8; i++) s += sb[i];
        sb[8] = s;
    }
    __syncthreads();
    const float inv = rsqrtf(sb[8] * (1.0f / Dn) + 1e-5f);

    const float4 gv = *(const float4*)(gamma + tid * 4);
    const float4 bv = *(const float4*)(beta + tid * 4);
    float4 ov;
    ov.x = d0 * inv * gv.x + bv.x;
    ov.y = d1 * inv * gv.y + bv.y;
    ov.z = d2 * inv * gv.z + bv.z;
    ov.w = d3 * inv * gv.w + bv.w;
    *(float4*)(out + (size_t)row * Dn + tid * 4) = ov;
}

} // namespace enc

// ============================================================================
// kernel_launch
// ============================================================================
extern "C" void kernel_launch(void* const* d_in, const int* in_sizes, int n_in,
                              void* d_out, int out_size)
{
    using namespace enc;
    (void)in_sizes; (void)n_in; (void)out_size;

    const float* x    = (const float*)d_in[0];
    const float* mask = (const float*)d_in[1];
    const float* Wq   = (const float*)d_in[2];
    const float* bq   = (const float*)d_in[3];
    const float* Wk   = (const float*)d_in[4];
    const float* bk   = (const float*)d_in[5];
    const float* Wv   = (const float*)d_in[6];
    const float* bv   = (const float*)d_in[7];
    const float* Wo   = (const float*)d_in[8];
    const float* bo   = (const float*)d_in[9];
    const float* W1   = (const float*)d_in[10];
    const float* b1   = (const float*)d_in[11];
    const float* W2   = (const float*)d_in[12];
    const float* b2   = (const float*)d_in[13];
    const float* g1   = (const float*)d_in[14];
    const float* be1  = (const float*)d_in[15];
    const float* g2   = (const float*)d_in[16];
    const float* be2  = (const float*)d_in[17];
    float* out = (float*)d_out;

    float *q, *k, *v, *o, *r, *x1, *h;
    cudaGetSymbolAddress((void**)&q,  g_q);
    cudaGetSymbolAddress((void**)&k,  g_k);
    cudaGetSymbolAddress((void**)&v,  g_v);
    cudaGetSymbolAddress((void**)&o,  g_o);
    cudaGetSymbolAddress((void**)&r,  g_r);
    cudaGetSymbolAddress((void**)&x1, g_x1);
    cudaGetSymbolAddress((void**)&h,  g_h);

    cudaFuncSetAttribute(gemm_qkv_kernel,
                         cudaFuncAttributeMaxDynamicSharedMemorySize, GEMM_SMEM);
    cudaFuncSetAttribute(gemm_kernel<false, true>,
                         cudaFuncAttributeMaxDynamicSharedMemorySize, GEMM_SMEM);
    cudaFuncSetAttribute(gemm_kernel<true, false>,
                         cudaFuncAttributeMaxDynamicSharedMemorySize, GEMM_SMEM);
    cudaFuncSetAttribute(flash_kernel,
                         cudaFuncAttributeMaxDynamicSharedMemorySize, FLASH_SMEM);

    const dim3 gQKV(24, 64);
    const dim3 gD(Dn / 128, Mn / 128);
    const dim3 gF(DFFn / 128, Mn / 128);

    // fused QKV projections (one 1536-CTA launch)
    gemm_qkv_kernel<<<gQKV, 256, GEMM_SMEM>>>(x, Wq, bq, Wk, bk, Wv, bv, q, k, v);

    // attention
    flash_kernel<<<dim3(Sn / 64, Hn, Bn), 128, FLASH_SMEM>>>(q, k, v, mask, o);

    // O projection + residual, then LN1
    gemm_kernel<false, true><<<gD, 256, GEMM_SMEM>>>(o, Wo, bo, x, r, Dn, Dn);
    layernorm_kernel<<<Mn, 256>>>(r, g1, be1, x1);

    // FFN
    gemm_kernel<true, false><<<gF, 256, GEMM_SMEM>>>(x1, W1, b1, nullptr, h, DFFn, Dn);
    gemm_kernel<false, true><<<gD, 256, GEMM_SMEM>>>(h, W2, b2, x1, r, Dn, DFFn);
    layernorm_kernel<<<Mn, 256>>>(r, g2, be2, out);
}

// round 4
// speedup vs baseline: 1.1971x; 1.0557x over previous
#include <cuda_runtime.h>
#include <cuda_bf16.h>
#include <cstdint>

// ============================================================================
// EncoderLayer: x -> MHA(+resid,LN) -> FFN(+resid,LN)
// B=4, S=2048, D=1024, H=16, dk=64, FF=4096.  All GEMMs via tf32 mma.sync.
// R4: all tf32 rounding hoisted out of hot loops (pre-rounded operands),
//     GEMM raw-bit fragments + launch_bounds(256,2), flash K/V via cp.async
//     double buffering. Numerics bit-identical to R3.
// ============================================================================

namespace enc {

constexpr int Bn   = 4;
constexpr int Sn   = 2048;
constexpr int Dn   = 1024;
constexpr int Hn   = 16;
constexpr int DKn  = 64;
constexpr int DFFn = 4096;
constexpr int Mn   = Bn * Sn;

// Scratch (device globals; no cudaMalloc allowed)
__device__ float g_q  [Mn * Dn];
__device__ float g_k  [Mn * Dn];
__device__ float g_v  [Mn * Dn];
__device__ float g_o  [Mn * Dn];
__device__ float g_r  [Mn * Dn];
__device__ float g_x1 [Mn * Dn];
__device__ float g_x1r[Mn * Dn];
__device__ float g_xr [Mn * Dn];
__device__ float g_h  [Mn * DFFn];
// rounded weight copies
__device__ float g_wq [Dn * Dn];
__device__ float g_wk [Dn * Dn];
__device__ float g_wv [Dn * Dn];
__device__ float g_wo [Dn * Dn];
__device__ float g_w1 [DFFn * Dn];
__device__ float g_w2 [Dn * DFFn];

__device__ __forceinline__ uint32_t f2tf(float f) {
    uint32_t r;
    asm("cvt.rna.tf32.f32 %0, %1;" : "=r"(r) : "f"(f));
    return r;
}
__device__ __forceinline__ float roundtf(float f) {
    return __uint_as_float(f2tf(f));
}

__device__ __forceinline__ void mma_tf32(float c[4],
    uint32_t a0, uint32_t a1, uint32_t a2, uint32_t a3,
    uint32_t b0, uint32_t b1)
{
    asm volatile(
        "mma.sync.aligned.m16n8k8.row.col.f32.tf32.tf32.f32 "
        "{%0,%1,%2,%3}, {%4,%5,%6,%7}, {%8,%9}, {%0,%1,%2,%3};"
        : "+f"(c[0]), "+f"(c[1]), "+f"(c[2]), "+f"(c[3])
        : "r"(a0), "r"(a1), "r"(a2), "r"(a3), "r"(b0), "r"(b1));
}

__device__ __forceinline__ void cp16(float* smem_dst, const float* gsrc) {
    uint32_t sa = (uint32_t)__cvta_generic_to_shared(smem_dst);
    asm volatile("cp.async.cg.shared.global [%0], [%1], 16;\n"
                 :: "r"(sa), "l"(gsrc));
}
__device__ __forceinline__ void cp_commit() {
    asm volatile("cp.async.commit_group;\n");
}
template<int N>
__device__ __forceinline__ void cp_wait() {
    asm volatile("cp.async.wait_group %0;\n" :: "n"(N));
}

// ============================================================================
// Pre-round to tf32 (elementwise, float4)
// ============================================================================
__global__ __launch_bounds__(256)
void round_kernel(const float* __restrict__ src, float* __restrict__ dst, int n4)
{
    const int i = blockIdx.x * 256 + threadIdx.x;
    if (i < n4) {
        float4 v = ((const float4*)src)[i];
        float4 u;
        u.x = roundtf(v.x); u.y = roundtf(v.y);
        u.z = roundtf(v.z); u.w = roundtf(v.w);
        ((float4*)dst)[i] = u;
    }
}

// ============================================================================
// GEMM body: C tile = A[BM,K] @ W[BN,K]^T + bias (+resid)(+relu)(round out)
// BM=BN=128, BK=32, 3-stage cp.async pipeline, 256 thr (2x4 warps, 64x32).
// A and W must be pre-rounded to tf32 values.
// ============================================================================
constexpr int GEMM_STAGES = 3;
constexpr int GEMM_LDS    = 36;
constexpr int GEMM_STAGE_F = 128 * GEMM_LDS;
constexpr int GEMM_SMEM = GEMM_STAGES * 2 * GEMM_STAGE_F * 4;

template<bool RELU, bool RESID, bool ROUND>
__device__ __forceinline__ void gemm_body(
    const float* __restrict__ A, const float* __restrict__ W,
    const float* __restrict__ bias, const float* __restrict__ resid,
    float* __restrict__ C, int N, int K, int bm, int bn, float* smem)
{
    constexpr int BK = 32;
    float* As = smem;
    float* Bs = smem + GEMM_STAGES * GEMM_STAGE_F;

    const int tid  = threadIdx.x;
    const int warp = tid >> 5, lane = tid & 31;
    const int wm = (warp >> 2) * 64;
    const int wn = (warp & 3) * 32;
    const int g = lane >> 2, t = lane & 3;

    int rowS[4], colS[4];
    #pragma unroll
    for (int i = 0; i < 4; i++) {
        int idx = tid + i * 256;
        rowS[i] = idx >> 3;
        colS[i] = (idx & 7) * 4;
    }
    const float* Ap = A + (size_t)bm * K;
    const float* Wp = W + (size_t)bn * K;

    float acc[4][4][4];
    #pragma unroll
    for (int mf = 0; mf < 4; mf++)
        #pragma unroll
        for (int nf = 0; nf < 4; nf++)
            #pragma unroll
            for (int e = 0; e < 4; e++) acc[mf][nf][e] = 0.0f;

    const int T = K / BK;

    #pragma unroll
    for (int s = 0; s < GEMM_STAGES - 1; s++) {
        float* as = As + s * GEMM_STAGE_F;
        float* bs = Bs + s * GEMM_STAGE_F;
        const int k0 = s * BK;
        #pragma unroll
        for (int i = 0; i < 4; i++) {
            cp16(as + rowS[i] * GEMM_LDS + colS[i], Ap + (size_t)rowS[i] * K + k0 + colS[i]);
            cp16(bs + rowS[i] * GEMM_LDS + colS[i], Wp + (size_t)rowS[i] * K + k0 + colS[i]);
        }
        cp_commit();
    }

    for (int kt = 0; kt < T; kt++) {
        cp_wait<GEMM_STAGES - 2>();
        __syncthreads();

        if (kt + GEMM_STAGES - 1 < T) {
            const int s = (kt + GEMM_STAGES - 1) % GEMM_STAGES;
            float* as = As + s * GEMM_STAGE_F;
            float* bs = Bs + s * GEMM_STAGE_F;
            const int k0 = (kt + GEMM_STAGES - 1) * BK;
            #pragma unroll
            for (int i = 0; i < 4; i++) {
                cp16(as + rowS[i] * GEMM_LDS + colS[i], Ap + (size_t)rowS[i] * K + k0 + colS[i]);
                cp16(bs + rowS[i] * GEMM_LDS + colS[i], Wp + (size_t)rowS[i] * K + k0 + colS[i]);
            }
        }
        cp_commit();

        const float* as = As + (kt % GEMM_STAGES) * GEMM_STAGE_F;
        const float* bs = Bs + (kt % GEMM_STAGES) * GEMM_STAGE_F;

        #pragma unroll
        for (int ks = 0; ks < 4; ks++) {
            uint32_t af[4][4], bf[4][2];
            const int c = ks * 8 + t;
            #pragma unroll
            for (int mf = 0; mf < 4; mf++) {
                const int r0 = (wm + mf * 16 + g) * GEMM_LDS;
                const int r1 = r0 + 8 * GEMM_LDS;
                af[mf][0] = __float_as_uint(as[r0 + c]);
                af[mf][1] = __float_as_uint(as[r1 + c]);
                af[mf][2] = __float_as_uint(as[r0 + c + 4]);
                af[mf][3] = __float_as_uint(as[r1 + c + 4]);
            }
            #pragma unroll
            for (int nf = 0; nf < 4; nf++) {
                const int nr = (wn + nf * 8 + g) * GEMM_LDS;
                bf[nf][0] = __float_as_uint(bs[nr + c]);
                bf[nf][1] = __float_as_uint(bs[nr + c + 4]);
            }
            #pragma unroll
            for (int mf = 0; mf < 4; mf++)
                #pragma unroll
                for (int nf = 0; nf < 4; nf++)
                    mma_tf32(acc[mf][nf], af[mf][0], af[mf][1], af[mf][2], af[mf][3],
                             bf[nf][0], bf[nf][1]);
        }
    }

    // epilogue
    #pragma unroll
    for (int mf = 0; mf < 4; mf++) {
        const int row0 = bm + wm + mf * 16 + g;
        #pragma unroll
        for (int nf = 0; nf < 4; nf++) {
            const int col = bn + wn + nf * 8 + 2 * t;
            const float b0 = bias[col], b1 = bias[col + 1];
            float v0 = acc[mf][nf][0] + b0;
            float v1 = acc[mf][nf][1] + b1;
            float v2 = acc[mf][nf][2] + b0;
            float v3 = acc[mf][nf][3] + b1;
            if (RESID) {
                const float2 r0v = *(const float2*)(resid + (size_t)row0 * N + col);
                const float2 r1v = *(const float2*)(resid + (size_t)(row0 + 8) * N + col);
                v0 += r0v.x; v1 += r0v.y;
                v2 += r1v.x; v3 += r1v.y;
            }
            if (RELU) {
                v0 = fmaxf(v0, 0.0f); v1 = fmaxf(v1, 0.0f);
                v2 = fmaxf(v2, 0.0f); v3 = fmaxf(v3, 0.0f);
            }
            if (ROUND) {
                v0 = roundtf(v0); v1 = roundtf(v1);
                v2 = roundtf(v2); v3 = roundtf(v3);
            }
            *(float2*)(&C[(size_t)row0 * N + col])       = make_float2(v0, v1);
            *(float2*)(&C[(size_t)(row0 + 8) * N + col]) = make_float2(v2, v3);
        }
    }
}

template<bool RELU, bool RESID, bool ROUND>
__global__ __launch_bounds__(256, 2)
void gemm_kernel(const float* __restrict__ A, const float* __restrict__ W,
                 const float* __restrict__ bias, const float* __restrict__ resid,
                 float* __restrict__ C, int N, int K)
{
    extern __shared__ float smem[];
    gemm_body<RELU, RESID, ROUND>(A, W, bias, resid, C, N, K,
                                  blockIdx.y * 128, blockIdx.x * 128, smem);
}

// Fused QKV: one launch, blockIdx.x in [0,24): sel = x/8 picks {q,k,v}
__global__ __launch_bounds__(256, 2)
void gemm_qkv_kernel(const float* __restrict__ x,
                     const float* __restrict__ Wq, const float* __restrict__ bq,
                     const float* __restrict__ Wk, const float* __restrict__ bk,
                     const float* __restrict__ Wv, const float* __restrict__ bv,
                     float* __restrict__ q, float* __restrict__ k, float* __restrict__ v)
{
    extern __shared__ float smem[];
    const int sel = blockIdx.x >> 3;
    const int bx  = blockIdx.x & 7;
    const float* W = (sel == 0) ? Wq : (sel == 1) ? Wk : Wv;
    const float* b = (sel == 0) ? bq : (sel == 1) ? bk : bv;
    float*       C = (sel == 0) ? q  : (sel == 1) ? k  : v;
    gemm_body<false, false, true>(x, W, b, nullptr, C, Dn, Dn,
                                  blockIdx.y * 128, bx * 128, smem);
}

// ============================================================================
// Flash attention. CTA = (64 q-rows, head, batch), 128 threads.
// Inputs q/k/v pre-rounded to tf32. K/V/mask double-buffered via cp.async.
// Output o rounded to tf32 (consumed by Wo GEMM).
// ============================================================================
constexpr int FLD = 68;
constexpr int F_TILE = 64 * FLD;
constexpr int FLASH_SMEM = (5 * F_TILE + 128) * 4;   // Qs/Ps, Ks[2], Vs[2], Ms[2]

__global__ __launch_bounds__(128)
void flash_kernel(const float* __restrict__ Q, const float* __restrict__ Km,
                  const float* __restrict__ V, const float* __restrict__ mask,
                  float* __restrict__ O)
{
    extern __shared__ float sm[];
    float* Qs = sm;                      // reused as Ps after Q-frag extraction

    const int qt = blockIdx.x, h = blockIdx.y, b = blockIdx.z;
    const int tid = threadIdx.x;
    const int warp = tid >> 5, lane = tid & 31;
    const int g = lane >> 2, t = lane & 3;
    constexpr float SCALE = 0.125f;
    constexpr int T = Sn / 64;

    const float* Kb0 = Km + (size_t)(b * Sn) * Dn + h * DKn;
    const float* Vb0 = V  + (size_t)(b * Sn) * Dn + h * DKn;
    const float* Mb  = mask + b * Sn;

    auto stage = [&](int kt, int buf) {
        const float* Kb = Kb0 + (size_t)kt * 64 * Dn;
        const float* Vb = Vb0 + (size_t)kt * 64 * Dn;
        float* ks = sm + (1 + buf) * F_TILE;
        float* vs = sm + (3 + buf) * F_TILE;
        #pragma unroll
        for (int i = 0; i < 8; i++) {
            const int idx = tid + i * 128;
            const int r = idx >> 4, c4 = (idx & 15) * 4;
            cp16(ks + r * FLD + c4, Kb + (size_t)r * Dn + c4);
            cp16(vs + r * FLD + c4, Vb + (size_t)r * Dn + c4);
        }
        if (tid < 16) cp16(sm + 5 * F_TILE + buf * 64 + tid * 4, Mb + kt * 64 + tid * 4);
    };

    // load Q tile (pre-rounded tf32 values)
    const float* Qb = Q + (size_t)(b * Sn + qt * 64) * Dn + h * DKn;
    for (int i = tid; i < 64 * 16; i += 128) {
        const int r = i >> 4, c4 = (i & 15) * 4;
        *(float4*)(&Qs[r * FLD + c4]) = *(const float4*)(Qb + (size_t)r * Dn + c4);
    }

    // prologue of the K/V pipeline
    stage(0, 0);
    cp_commit();
    __syncthreads();

    // extract Q fragments (raw bits — already tf32)
    const int prow0 = (warp * 16 + g) * FLD;
    const int prow1 = prow0 + 8 * FLD;
    uint32_t aq[8][4];
    #pragma unroll
    for (int ks = 0; ks < 8; ks++) {
        const int c = ks * 8 + t;
        aq[ks][0] = __float_as_uint(Qs[prow0 + c]);
        aq[ks][1] = __float_as_uint(Qs[prow1 + c]);
        aq[ks][2] = __float_as_uint(Qs[prow0 + c + 4]);
        aq[ks][3] = __float_as_uint(Qs[prow1 + c + 4]);
    }
    __syncthreads();
    float* Ps = Qs;

    float m0 = -1e30f, m1 = -1e30f, l0 = 0.0f, l1 = 0.0f;
    float o[8][4];
    #pragma unroll
    for (int nf = 0; nf < 8; nf++)
        #pragma unroll
        for (int e = 0; e < 4; e++) o[nf][e] = 0.0f;

    for (int kt = 0; kt < T; kt++) {
        if (kt + 1 < T) stage(kt + 1, (kt + 1) & 1);
        cp_commit();
        cp_wait<1>();
        __syncthreads();

        const float* Ks = sm + (1 + (kt & 1)) * F_TILE;
        const float* Vs = sm + (3 + (kt & 1)) * F_TILE;
        const float* Ms = sm + 5 * F_TILE + (kt & 1) * 64;

        // S = Q K^T (warp owns 16 q-rows x 64 keys)
        float s[8][4];
        #pragma unroll
        for (int nf = 0; nf < 8; nf++)
            #pragma unroll
            for (int e = 0; e < 4; e++) s[nf][e] = 0.0f;

        #pragma unroll
        for (int ks = 0; ks < 8; ks++) {
            const int c = ks * 8 + t;
            #pragma unroll
            for (int nf = 0; nf < 8; nf++) {
                const int nr = (nf * 8 + g) * FLD;
                const uint32_t b0 = __float_as_uint(Ks[nr + c]);
                const uint32_t b1 = __float_as_uint(Ks[nr + c + 4]);
                mma_tf32(s[nf], aq[ks][0], aq[ks][1], aq[ks][2], aq[ks][3], b0, b1);
            }
        }

        // scale + mask + row max
        float rmax0 = -1e30f, rmax1 = -1e30f;
        #pragma unroll
        for (int nf = 0; nf < 8; nf++) {
            const float mk0 = Ms[nf * 8 + 2 * t];
            const float mk1 = Ms[nf * 8 + 2 * t + 1];
            s[nf][0] = s[nf][0] * SCALE + mk0;
            s[nf][1] = s[nf][1] * SCALE + mk1;
            s[nf][2] = s[nf][2] * SCALE + mk0;
            s[nf][3] = s[nf][3] * SCALE + mk1;
            rmax0 = fmaxf(rmax0, fmaxf(s[nf][0], s[nf][1]));
            rmax1 = fmaxf(rmax1, fmaxf(s[nf][2], s[nf][3]));
        }
        rmax0 = fmaxf(rmax0, __shfl_xor_sync(0xffffffffu, rmax0, 1));
        rmax0 = fmaxf(rmax0, __shfl_xor_sync(0xffffffffu, rmax0, 2));
        rmax1 = fmaxf(rmax1, __shfl_xor_sync(0xffffffffu, rmax1, 1));
        rmax1 = fmaxf(rmax1, __shfl_xor_sync(0xffffffffu, rmax1, 2));

        const float mn0 = fmaxf(m0, rmax0), mn1 = fmaxf(m1, rmax1);
        const float sc0 = __expf(m0 - mn0), sc1 = __expf(m1 - mn1);

        float rs0 = 0.0f, rs1 = 0.0f;
        #pragma unroll
        for (int nf = 0; nf < 8; nf++) {
            s[nf][0] = __expf(s[nf][0] - mn0);
            s[nf][1] = __expf(s[nf][1] - mn0);
            s[nf][2] = __expf(s[nf][2] - mn1);
            s[nf][3] = __expf(s[nf][3] - mn1);
            rs0 += s[nf][0] + s[nf][1];
            rs1 += s[nf][2] + s[nf][3];
        }
        rs0 += __shfl_xor_sync(0xffffffffu, rs0, 1);
        rs0 += __shfl_xor_sync(0xffffffffu, rs0, 2);
        rs1 += __shfl_xor_sync(0xffffffffu, rs1, 1);
        rs1 += __shfl_xor_sync(0xffffffffu, rs1, 2);

        l0 = l0 * sc0 + rs0;
        l1 = l1 * sc1 + rs1;
        m0 = mn0; m1 = mn1;

        #pragma unroll
        for (int nf = 0; nf < 8; nf++) {
            o[nf][0] *= sc0; o[nf][1] *= sc0;
            o[nf][2] *= sc1; o[nf][3] *= sc1;
        }

        // P -> warp-private smem rows (stored pre-converted to tf32)
        #pragma unroll
        for (int nf = 0; nf < 8; nf++) {
            const int c = nf * 8 + 2 * t;
            *(uint2*)(&Ps[prow0 + c]) = make_uint2(f2tf(s[nf][0]), f2tf(s[nf][1]));
            *(uint2*)(&Ps[prow1 + c]) = make_uint2(f2tf(s[nf][2]), f2tf(s[nf][3]));
        }
        __syncwarp();

        // O += P V
        #pragma unroll
        for (int ks = 0; ks < 8; ks++) {
            const int c = ks * 8 + t;
            const uint32_t a0 = __float_as_uint(Ps[prow0 + c]);
            const uint32_t a1 = __float_as_uint(Ps[prow1 + c]);
            const uint32_t a2 = __float_as_uint(Ps[prow0 + c + 4]);
            const uint32_t a3 = __float_as_uint(Ps[prow1 + c + 4]);
            #pragma unroll
            for (int nf = 0; nf < 8; nf++) {
                const uint32_t b0 = __float_as_uint(Vs[(c)     * FLD + nf * 8 + g]);
                const uint32_t b1 = __float_as_uint(Vs[(c + 4) * FLD + nf * 8 + g]);
                mma_tf32(o[nf], a0, a1, a2, a3, b0, b1);
            }
        }
        __syncthreads();
    }

    const float inv0 = 1.0f / l0, inv1 = 1.0f / l1;
    const int orow0 = b * Sn + qt * 64 + warp * 16 + g;
    #pragma unroll
    for (int nf = 0; nf < 8; nf++) {
        const int col = h * DKn + nf * 8 + 2 * t;
        *(float2*)(&O[(size_t)orow0 * Dn + col]) =
            make_float2(roundtf(o[nf][0] * inv0), roundtf(o[nf][1] * inv0));
        *(float2*)(&O[(size_t)(orow0 + 8) * Dn + col]) =
            make_float2(roundtf(o[nf][2] * inv1), roundtf(o[nf][3] * inv1));
    }
}

// ============================================================================
// LayerNorm over rows of 1024. One block (256 thr) per row, two-pass.
// Optionally also writes a tf32-rounded copy (GEMM A input for next layer).
// ============================================================================
__global__ __launch_bounds__(256)
void layernorm_kernel(const float* __restrict__ in, const float* __restrict__ gamma,
                      const float* __restrict__ beta, float* __restrict__ out,
                      float* __restrict__ rout)
{
    __shared__ float sb[9];
    const int row = blockIdx.x;
    const int tid = threadIdx.x;
    const float4 xv = *(const float4*)(in + (size_t)row * Dn + tid * 4);

    float ssum = xv.x + xv.y + xv.z + xv.w;
    #pragma unroll
    for (int off = 16; off; off >>= 1) ssum += __shfl_xor_sync(0xffffffffu, ssum, off);
    if ((tid & 31) == 0) sb[tid >> 5] = ssum;
    __syncthreads();
    if (tid == 0) {
        float s = 0.0f;
        #pragma unroll
        for (int i = 0; i < 8; i++) s += sb[i];
        sb[8] = s;
    }
    __syncthreads();
    const float mu = sb[8] * (1.0f / Dn);

    const float d0 = xv.x - mu, d1 = xv.y - mu, d2 = xv.z - mu, d3 = xv.w - mu;
    float sq = d0 * d0 + d1 * d1 + d2 * d2 + d3 * d3;
    __syncthreads();
    #pragma unroll
    for (int off = 16; off; off >>= 1) sq += __shfl_xor_sync(0xffffffffu, sq, off);
    if ((tid & 31) == 0) sb[tid >> 5] = sq;
    __syncthreads();
    if (tid == 0) {
        float s = 0.0f;
        #pragma unroll
        for (int i = 0; i < 8; i++) s += sb[i];
        sb[8] = s;
    }
    __syncthreads();
    const float inv = rsqrtf(sb[8] * (1.0f / Dn) + 1e-5f);

    const float4 gv = *(const float4*)(gamma + tid * 4);
    const float4 bv = *(const float4*)(beta + tid * 4);
    float4 ov;
    ov.x = d0 * inv * gv.x + bv.x;
    ov.y = d1 * inv * gv.y + bv.y;
    ov.z = d2 * inv * gv.z + bv.z;
    ov.w = d3 * inv * gv.w + bv.w;
    *(float4*)(out + (size_t)row * Dn + tid * 4) = ov;
    if (rout) {
        float4 rv;
        rv.x = roundtf(ov.x); rv.y = roundtf(ov.y);
        rv.z = roundtf(ov.z); rv.w = roundtf(ov.w);
        *(float4*)(rout + (size_t)row * Dn + tid * 4) = rv;
    }
}

} // namespace enc

// ============================================================================
// kernel_launch
// ============================================================================
extern "C" void kernel_launch(void* const* d_in, const int* in_sizes, int n_in,
                              void* d_out, int out_size)
{
    using namespace enc;
    (void)in_sizes; (void)n_in; (void)out_size;

    const float* x    = (const float*)d_in[0];
    const float* mask = (const float*)d_in[1];
    const float* Wq   = (const float*)d_in[2];
    const float* bq   = (const float*)d_in[3];
    const float* Wk   = (const float*)d_in[4];
    const float* bk   = (const float*)d_in[5];
    const float* Wv   = (const float*)d_in[6];
    const float* bv   = (const float*)d_in[7];
    const float* Wo   = (const float*)d_in[8];
    const float* bo   = (const float*)d_in[9];
    const float* W1   = (const float*)d_in[10];
    const float* b1   = (const float*)d_in[11];
    const float* W2   = (const float*)d_in[12];
    const float* b2   = (const float*)d_in[13];
    const float* g1   = (const float*)d_in[14];
    const float* be1  = (const float*)d_in[15];
    const float* g2   = (const float*)d_in[16];
    const float* be2  = (const float*)d_in[17];
    float* out = (float*)d_out;

    float *q, *k, *v, *o, *r, *x1, *x1r, *xr, *h;
    float *wq, *wk, *wv, *wo, *w1, *w2;
    cudaGetSymbolAddress((void**)&q,   g_q);
    cudaGetSymbolAddress((void**)&k,   g_k);
    cudaGetSymbolAddress((void**)&v,   g_v);
    cudaGetSymbolAddress((void**)&o,   g_o);
    cudaGetSymbolAddress((void**)&r,   g_r);
    cudaGetSymbolAddress((void**)&x1,  g_x1);
    cudaGetSymbolAddress((void**)&x1r, g_x1r);
    cudaGetSymbolAddress((void**)&xr,  g_xr);
    cudaGetSymbolAddress((void**)&h,   g_h);
    cudaGetSymbolAddress((void**)&wq,  g_wq);
    cudaGetSymbolAddress((void**)&wk,  g_wk);
    cudaGetSymbolAddress((void**)&wv,  g_wv);
    cudaGetSymbolAddress((void**)&wo,  g_wo);
    cudaGetSymbolAddress((void**)&w1,  g_w1);
    cudaGetSymbolAddress((void**)&w2,  g_w2);

    cudaFuncSetAttribute(gemm_qkv_kernel,
                         cudaFuncAttributeMaxDynamicSharedMemorySize, GEMM_SMEM);
    cudaFuncSetAttribute(gemm_kernel<false, true, false>,
                         cudaFuncAttributeMaxDynamicSharedMemorySize, GEMM_SMEM);
    cudaFuncSetAttribute(gemm_kernel<true, false, true>,
                         cudaFuncAttributeMaxDynamicSharedMemorySize, GEMM_SMEM);
    cudaFuncSetAttribute(flash_kernel,
                         cudaFuncAttributeMaxDynamicSharedMemorySize, FLASH_SMEM);

    // ---- prep: round weights + x to tf32 (one-time per call) ----
    const int nD  = Dn * Dn / 4;          // 262144
    const int nF  = DFFn * Dn / 4;        // 1048576
    const int nX  = Mn * Dn / 4;          // 2097152
    round_kernel<<<(nD + 255) / 256, 256>>>(Wq, wq, nD);
    round_kernel<<<(nD + 255) / 256, 256>>>(Wk, wk, nD);
    round_kernel<<<(nD + 255) / 256, 256>>>(Wv, wv, nD);
    round_kernel<<<(nD + 255) / 256, 256>>>(Wo, wo, nD);
    round_kernel<<<(nF + 255) / 256, 256>>>(W1, w1, nF);
    round_kernel<<<(nF + 255) / 256, 256>>>(W2, w2, nF);
    round_kernel<<<(nX + 255) / 256, 256>>>(x,  xr, nX);

    const dim3 gQKV(24, 64);
    const dim3 gD(Dn / 128, Mn / 128);
    const dim3 gF(DFFn / 128, Mn / 128);

    // fused QKV projections (outputs rounded to tf32)
    gemm_qkv_kernel<<<gQKV, 256, GEMM_SMEM>>>(xr, wq, bq, wk, bk, wv, bv, q, k, v);

    // attention (output o rounded)
    flash_kernel<<<dim3(Sn / 64, Hn, Bn), 128, FLASH_SMEM>>>(q, k, v, mask, o);

    // O projection + residual (exact out), then LN1 (exact + rounded out)
    gemm_kernel<false, true, false><<<gD, 256, GEMM_SMEM>>>(o, wo, bo, x, r, Dn, Dn);
    layernorm_kernel<<<Mn, 256>>>(r, g1, be1, x1, x1r);

    // FFN
    gemm_kernel<true, false, true><<<gF, 256, GEMM_SMEM>>>(x1r, w1, b1, nullptr, h, DFFn, Dn);
    gemm_kernel<false, true, false><<<gD, 256, GEMM_SMEM>>>(h, w2, b2, x1, r, Dn, DFFn);
    layernorm_kernel<<<Mn, 256>>>(r, g2, be2, out, nullptr);
}

// round 6
// speedup vs baseline: 1.6455x; 1.3745x over previous
#include <cuda_runtime.h>
#include <cuda_fp16.h>
#include <cstdint>

// ============================================================================
// EncoderLayer: x -> MHA(+resid,LN) -> FFN(+resid,LN)
// B=4, S=2048, D=1024, H=16, dk=64, FF=4096.
// R6 (= R5 resubmit; infra failure last round):
//   dense GEMMs via fp16 mma.sync.m16n8k16 (fp32 accum) — 2x tf32 throughput
//   at the SAME 11-bit operand precision. Flash attention stays tf32.
//   All input conversions fused into one prep kernel.
// ============================================================================

namespace enc {

constexpr int Bn   = 4;
constexpr int Sn   = 2048;
constexpr int Dn   = 1024;
constexpr int Hn   = 16;
constexpr int DKn  = 64;
constexpr int DFFn = 4096;
constexpr int Mn   = Bn * Sn;

// Scratch (device globals; no cudaMalloc allowed)
__device__ float  g_q  [Mn * Dn];     // flash inputs (tf32-valued f32)
__device__ float  g_k  [Mn * Dn];
__device__ float  g_v  [Mn * Dn];
__device__ float  g_r  [Mn * Dn];     // pre-LN residual sum
__device__ float  g_x1 [Mn * Dn];     // LN1 output (f32, residual for FF2)
__device__ __half g_oh [Mn * Dn];     // flash output (A of O-proj)
__device__ __half g_x1h[Mn * Dn];     // LN1 output fp16 (A of FF1)
__device__ __half g_xh [Mn * Dn];     // x fp16 (A of QKV)
__device__ __half g_hh [Mn * DFFn];   // FFN hidden fp16 (A of FF2)
// fp16 weight copies
__device__ __half g_wq [Dn * Dn];
__device__ __half g_wk [Dn * Dn];
__device__ __half g_wv [Dn * Dn];
__device__ __half g_wo [Dn * Dn];
__device__ __half g_w1 [DFFn * Dn];
__device__ __half g_w2 [Dn * DFFn];

__device__ __forceinline__ uint32_t f2tf(float f) {
    uint32_t r;
    asm("cvt.rna.tf32.f32 %0, %1;" : "=r"(r) : "f"(f));
    return r;
}
__device__ __forceinline__ float roundtf(float f) {
    return __uint_as_float(f2tf(f));
}

// tf32 m16n8k8 (flash)
__device__ __forceinline__ void mma_tf32(float c[4],
    uint32_t a0, uint32_t a1, uint32_t a2, uint32_t a3,
    uint32_t b0, uint32_t b1)
{
    asm volatile(
        "mma.sync.aligned.m16n8k8.row.col.f32.tf32.tf32.f32 "
        "{%0,%1,%2,%3}, {%4,%5,%6,%7}, {%8,%9}, {%0,%1,%2,%3};"
        : "+f"(c[0]), "+f"(c[1]), "+f"(c[2]), "+f"(c[3])
        : "r"(a0), "r"(a1), "r"(a2), "r"(a3), "r"(b0), "r"(b1));
}

// fp16 m16n8k16 (dense GEMMs), fp32 accumulate
__device__ __forceinline__ void mma_f16(float c[4],
    uint32_t a0, uint32_t a1, uint32_t a2, uint32_t a3,
    uint32_t b0, uint32_t b1)
{
    asm volatile(
        "mma.sync.aligned.m16n8k16.row.col.f32.f16.f16.f32 "
        "{%0,%1,%2,%3}, {%4,%5,%6,%7}, {%8,%9}, {%0,%1,%2,%3};"
        : "+f"(c[0]), "+f"(c[1]), "+f"(c[2]), "+f"(c[3])
        : "r"(a0), "r"(a1), "r"(a2), "r"(a3), "r"(b0), "r"(b1));
}

__device__ __forceinline__ void cp16(void* smem_dst, const void* gsrc) {
    uint32_t sa = (uint32_t)__cvta_generic_to_shared(smem_dst);
    asm volatile("cp.async.cg.shared.global [%0], [%1], 16;\n"
                 :: "r"(sa), "l"(gsrc));
}
__device__ __forceinline__ void cp_commit() {
    asm volatile("cp.async.commit_group;\n");
}
template<int N>
__device__ __forceinline__ void cp_wait() {
    asm volatile("cp.async.wait_group %0;\n" :: "n"(N));
}

// ============================================================================
// Fused conversion: all 6 weights + x -> fp16, ONE launch.
// Region table in float4 units.
// ============================================================================
constexpr int CN_D = Dn * Dn / 4;        // 262144
constexpr int CN_F = DFFn * Dn / 4;      // 1048576
constexpr int CN_X = Mn * Dn / 4;        // 2097152
constexpr int CN_TOTAL = 4 * CN_D + 2 * CN_F + CN_X;   // 5242880

__global__ __launch_bounds__(256)
void convert_all_kernel(const float* __restrict__ Wq, const float* __restrict__ Wk,
                        const float* __restrict__ Wv, const float* __restrict__ Wo,
                        const float* __restrict__ W1, const float* __restrict__ W2,
                        const float* __restrict__ x,
                        __half* wq, __half* wk, __half* wv, __half* wo,
                        __half* w1, __half* w2, __half* xh)
{
    int idx = blockIdx.x * 256 + threadIdx.x;
    if (idx >= CN_TOTAL) return;
    const float* src; __half* dst;
    if      (idx <  CN_D)                       { src = Wq; dst = wq; }
    else if ((idx -= CN_D) < CN_D)              { src = Wk; dst = wk; }
    else if ((idx -= CN_D) < CN_D)              { src = Wv; dst = wv; }
    else if ((idx -= CN_D) < CN_D)              { src = Wo; dst = wo; }
    else if ((idx -= CN_D) < CN_F)              { src = W1; dst = w1; }
    else if ((idx -= CN_F) < CN_F)              { src = W2; dst = w2; }
    else     { idx -= CN_F;                       src = x;  dst = xh; }

    const float4 v = ((const float4*)src)[idx];
    __half2 h0 = __float22half2_rn(make_float2(v.x, v.y));
    __half2 h1 = __float22half2_rn(make_float2(v.z, v.w));
    ((__half2*)dst)[idx * 2]     = h0;
    ((__half2*)dst)[idx * 2 + 1] = h1;
}

// ============================================================================
// fp16 GEMM: C tile = A[BM,K] @ W[BN,K]^T + bias (+resid)(+relu)
// BM=BN=128, BK=32 halves, 3-stage cp.async, 256 thr (2x4 warps, 64x32 tiles).
// Output: f32 C (optionally tf32-rounded) and/or fp16 Ch.
// ============================================================================
constexpr int GEMM_STAGES = 3;
constexpr int GLDSH    = 40;                // halves per smem row (32 + 8 pad)
constexpr int G_STAGE  = 128 * GLDSH;       // halves per tile-stage
constexpr int GEMM_SMEM = GEMM_STAGES * 2 * G_STAGE * 2;   // bytes = 61440

template<bool RELU, bool RESID, bool ROUND, bool WF32, bool WHALF>
__device__ __forceinline__ void gemm_body(
    const __half* __restrict__ A, const __half* __restrict__ W,
    const float* __restrict__ bias, const float* __restrict__ resid,
    float* __restrict__ C, __half* __restrict__ Ch,
    int N, int K, int bm, int bn, __half* smem)
{
    constexpr int BK = 32;                  // halves of K per stage
    __half* As = smem;
    __half* Bs = smem + GEMM_STAGES * G_STAGE;

    const int tid  = threadIdx.x;
    const int warp = tid >> 5, lane = tid & 31;
    const int wm = (warp >> 2) * 64;
    const int wn = (warp & 3) * 32;
    const int g = lane >> 2, t = lane & 3;

    // staging map: 512 x 16B chunks per tile; 2 per thread per tile
    int rowS[2], colS[2];
    #pragma unroll
    for (int i = 0; i < 2; i++) {
        const int idx = tid + i * 256;      // 0..511
        rowS[i] = idx >> 2;
        colS[i] = (idx & 3) * 8;            // halves
    }
    const __half* Ap = A + (size_t)bm * K;
    const __half* Wp = W + (size_t)bn * K;

    float acc[4][4][4];
    #pragma unroll
    for (int mf = 0; mf < 4; mf++)
        #pragma unroll
        for (int nf = 0; nf < 4; nf++)
            #pragma unroll
            for (int e = 0; e < 4; e++) acc[mf][nf][e] = 0.0f;

    const int T = K / BK;

    #pragma unroll
    for (int s = 0; s < GEMM_STAGES - 1; s++) {
        __half* as = As + s * G_STAGE;
        __half* bs = Bs + s * G_STAGE;
        const int k0 = s * BK;
        #pragma unroll
        for (int i = 0; i < 2; i++) {
            cp16(as + rowS[i] * GLDSH + colS[i], Ap + (size_t)rowS[i] * K + k0 + colS[i]);
            cp16(bs + rowS[i] * GLDSH + colS[i], Wp + (size_t)rowS[i] * K + k0 + colS[i]);
        }
        cp_commit();
    }

    for (int kt = 0; kt < T; kt++) {
        cp_wait<GEMM_STAGES - 2>();
        __syncthreads();

        if (kt + GEMM_STAGES - 1 < T) {
            const int s = (kt + GEMM_STAGES - 1) % GEMM_STAGES;
            __half* as = As + s * G_STAGE;
            __half* bs = Bs + s * G_STAGE;
            const int k0 = (kt + GEMM_STAGES - 1) * BK;
            #pragma unroll
            for (int i = 0; i < 2; i++) {
                cp16(as + rowS[i] * GLDSH + colS[i], Ap + (size_t)rowS[i] * K + k0 + colS[i]);
                cp16(bs + rowS[i] * GLDSH + colS[i], Wp + (size_t)rowS[i] * K + k0 + colS[i]);
            }
        }
        cp_commit();

        const uint32_t* a32 = (const uint32_t*)(As + (kt % GEMM_STAGES) * G_STAGE);
        const uint32_t* b32 = (const uint32_t*)(Bs + (kt % GEMM_STAGES) * G_STAGE);

        #pragma unroll
        for (int kstep = 0; kstep < 2; kstep++) {     // 2 x K16 per BK=32
            const int kb2 = kstep * 8;                // u32 offset (16 halves)
            uint32_t af[4][4], bf[4][2];
            #pragma unroll
            for (int mf = 0; mf < 4; mf++) {
                const uint32_t* ar0 = a32 + (wm + mf * 16 + g) * 20;
                const uint32_t* ar1 = ar0 + 8 * 20;
                af[mf][0] = ar0[kb2 + t];
                af[mf][1] = ar1[kb2 + t];
                af[mf][2] = ar0[kb2 + t + 4];
                af[mf][3] = ar1[kb2 + t + 4];
            }
            #pragma unroll
            for (int nf = 0; nf < 4; nf++) {
                const uint32_t* br = b32 + (wn + nf * 8 + g) * 20;
                bf[nf][0] = br[kb2 + t];
                bf[nf][1] = br[kb2 + t + 4];
            }
            #pragma unroll
            for (int mf = 0; mf < 4; mf++)
                #pragma unroll
                for (int nf = 0; nf < 4; nf++)
                    mma_f16(acc[mf][nf], af[mf][0], af[mf][1], af[mf][2], af[mf][3],
                            bf[nf][0], bf[nf][1]);
        }
    }

    // epilogue
    #pragma unroll
    for (int mf = 0; mf < 4; mf++) {
        const int row0 = bm + wm + mf * 16 + g;
        #pragma unroll
        for (int nf = 0; nf < 4; nf++) {
            const int col = bn + wn + nf * 8 + 2 * t;
            const float b0 = bias[col], b1 = bias[col + 1];
            float v0 = acc[mf][nf][0] + b0;
            float v1 = acc[mf][nf][1] + b1;
            float v2 = acc[mf][nf][2] + b0;
            float v3 = acc[mf][nf][3] + b1;
            if (RESID) {
                const float2 r0v = *(const float2*)(resid + (size_t)row0 * N + col);
                const float2 r1v = *(const float2*)(resid + (size_t)(row0 + 8) * N + col);
                v0 += r0v.x; v1 += r0v.y;
                v2 += r1v.x; v3 += r1v.y;
            }
            if (RELU) {
                v0 = fmaxf(v0, 0.0f); v1 = fmaxf(v1, 0.0f);
                v2 = fmaxf(v2, 0.0f); v3 = fmaxf(v3, 0.0f);
            }
            if (WF32) {
                float u0 = v0, u1 = v1, u2 = v2, u3 = v3;
                if (ROUND) {
                    u0 = roundtf(u0); u1 = roundtf(u1);
                    u2 = roundtf(u2); u3 = roundtf(u3);
                }
                *(float2*)(&C[(size_t)row0 * N + col])       = make_float2(u0, u1);
                *(float2*)(&C[(size_t)(row0 + 8) * N + col]) = make_float2(u2, u3);
            }
            if (WHALF) {
                *(__half2*)(&Ch[(size_t)row0 * N + col]) =
                    __float22half2_rn(make_float2(v0, v1));
                *(__half2*)(&Ch[(size_t)(row0 + 8) * N + col]) =
                    __float22half2_rn(make_float2(v2, v3));
            }
        }
    }
}

template<bool RELU, bool RESID, bool ROUND, bool WF32, bool WHALF>
__global__ __launch_bounds__(256, 2)
void gemm_kernel(const __half* __restrict__ A, const __half* __restrict__ W,
                 const float* __restrict__ bias, const float* __restrict__ resid,
                 float* __restrict__ C, __half* __restrict__ Ch, int N, int K)
{
    extern __shared__ __half smem[];
    gemm_body<RELU, RESID, ROUND, WF32, WHALF>(A, W, bias, resid, C, Ch, N, K,
                                               blockIdx.y * 128, blockIdx.x * 128, smem);
}

// Fused QKV: one launch; outputs tf32-rounded f32 (flash inputs)
__global__ __launch_bounds__(256, 2)
void gemm_qkv_kernel(const __half* __restrict__ x,
                     const __half* __restrict__ Wq, const float* __restrict__ bq,
                     const __half* __restrict__ Wk, const float* __restrict__ bk,
                     const __half* __restrict__ Wv, const float* __restrict__ bv,
                     float* __restrict__ q, float* __restrict__ k, float* __restrict__ v)
{
    extern __shared__ __half smem[];
    const int sel = blockIdx.x >> 3;
    const int bx  = blockIdx.x & 7;
    const __half* W = (sel == 0) ? Wq : (sel == 1) ? Wk : Wv;
    const float*  b = (sel == 0) ? bq : (sel == 1) ? bk : bv;
    float*        C = (sel == 0) ? q  : (sel == 1) ? k  : v;
    gemm_body<false, false, true, true, false>(x, W, b, nullptr, C, nullptr, Dn, Dn,
                                               blockIdx.y * 128, bx * 128, smem);
}

// ============================================================================
// Flash attention (tf32 path, unchanged numerics). CTA = (64 q, head, batch),
// 128 thr. K/V/mask double-buffered via cp.async. Output fp16 (A of O-proj).
// ============================================================================
constexpr int FLD = 68;
constexpr int F_TILE = 64 * FLD;
constexpr int FLASH_SMEM = (5 * F_TILE + 128) * 4;

__global__ __launch_bounds__(128)
void flash_kernel(const float* __restrict__ Q, const float* __restrict__ Km,
                  const float* __restrict__ V, const float* __restrict__ mask,
                  __half* __restrict__ O)
{
    extern __shared__ float sm[];
    float* Qs = sm;

    const int qt = blockIdx.x, h = blockIdx.y, b = blockIdx.z;
    const int tid = threadIdx.x;
    const int warp = tid >> 5, lane = tid & 31;
    const int g = lane >> 2, t = lane & 3;
    constexpr float SCALE = 0.125f;
    constexpr int T = Sn / 64;

    const float* Kb0 = Km + (size_t)(b * Sn) * Dn + h * DKn;
    const float* Vb0 = V  + (size_t)(b * Sn) * Dn + h * DKn;
    const float* Mb  = mask + b * Sn;

    auto stage = [&](int kt, int buf) {
        const float* Kb = Kb0 + (size_t)kt * 64 * Dn;
        const float* Vb = Vb0 + (size_t)kt * 64 * Dn;
        float* ks = sm + (1 + buf) * F_TILE;
        float* vs = sm + (3 + buf) * F_TILE;
        #pragma unroll
        for (int i = 0; i < 8; i++) {
            const int idx = tid + i * 128;
            const int r = idx >> 4, c4 = (idx & 15) * 4;
            cp16(ks + r * FLD + c4, Kb + (size_t)r * Dn + c4);
            cp16(vs + r * FLD + c4, Vb + (size_t)r * Dn + c4);
        }
        if (tid < 16) cp16(sm + 5 * F_TILE + buf * 64 + tid * 4, Mb + kt * 64 + tid * 4);
    };

    const float* Qb = Q + (size_t)(b * Sn + qt * 64) * Dn + h * DKn;
    for (int i = tid; i < 64 * 16; i += 128) {
        const int r = i >> 4, c4 = (i & 15) * 4;
        *(float4*)(&Qs[r * FLD + c4]) = *(const float4*)(Qb + (size_t)r * Dn + c4);
    }

    stage(0, 0);
    cp_commit();
    __syncthreads();

    const int prow0 = (warp * 16 + g) * FLD;
    const int prow1 = prow0 + 8 * FLD;
    uint32_t aq[8][4];
    #pragma unroll
    for (int ks = 0; ks < 8; ks++) {
        const int c = ks * 8 + t;
        aq[ks][0] = __float_as_uint(Qs[prow0 + c]);
        aq[ks][1] = __float_as_uint(Qs[prow1 + c]);
        aq[ks][2] = __float_as_uint(Qs[prow0 + c + 4]);
        aq[ks][3] = __float_as_uint(Qs[prow1 + c + 4]);
    }
    __syncthreads();
    float* Ps = Qs;

    float m0 = -1e30f, m1 = -1e30f, l0 = 0.0f, l1 = 0.0f;
    float o[8][4];
    #pragma unroll
    for (int nf = 0; nf < 8; nf++)
        #pragma unroll
        for (int e = 0; e < 4; e++) o[nf][e] = 0.0f;

    for (int kt = 0; kt < T; kt++) {
        if (kt + 1 < T) stage(kt + 1, (kt + 1) & 1);
        cp_commit();
        cp_wait<1>();
        __syncthreads();

        const float* Ks = sm + (1 + (kt & 1)) * F_TILE;
        const float* Vs = sm + (3 + (kt & 1)) * F_TILE;
        const float* Ms = sm + 5 * F_TILE + (kt & 1) * 64;

        float s[8][4];
        #pragma unroll
        for (int nf = 0; nf < 8; nf++)
            #pragma unroll
            for (int e = 0; e < 4; e++) s[nf][e] = 0.0f;

        #pragma unroll
        for (int ks = 0; ks < 8; ks++) {
            const int c = ks * 8 + t;
            #pragma unroll
            for (int nf = 0; nf < 8; nf++) {
                const int nr = (nf * 8 + g) * FLD;
                const uint32_t b0 = __float_as_uint(Ks[nr + c]);
                const uint32_t b1 = __float_as_uint(Ks[nr + c + 4]);
                mma_tf32(s[nf], aq[ks][0], aq[ks][1], aq[ks][2], aq[ks][3], b0, b1);
            }
        }

        float rmax0 = -1e30f, rmax1 = -1e30f;
        #pragma unroll
        for (int nf = 0; nf < 8; nf++) {
            const float mk0 = Ms[nf * 8 + 2 * t];
            const float mk1 = Ms[nf * 8 + 2 * t + 1];
            s[nf][0] = s[nf][0] * SCALE + mk0;
            s[nf][1] = s[nf][1] * SCALE + mk1;
            s[nf][2] = s[nf][2] * SCALE + mk0;
            s[nf][3] = s[nf][3] * SCALE + mk1;
            rmax0 = fmaxf(rmax0, fmaxf(s[nf][0], s[nf][1]));
            rmax1 = fmaxf(rmax1, fmaxf(s[nf][2], s[nf][3]));
        }
        rmax0 = fmaxf(rmax0, __shfl_xor_sync(0xffffffffu, rmax0, 1));
        rmax0 = fmaxf(rmax0, __shfl_xor_sync(0xffffffffu, rmax0, 2));
        rmax1 = fmaxf(rmax1, __shfl_xor_sync(0xffffffffu, rmax1, 1));
        rmax1 = fmaxf(rmax1, __shfl_xor_sync(0xffffffffu, rmax1, 2));

        const float mn0 = fmaxf(m0, rmax0), mn1 = fmaxf(m1, rmax1);
        const float sc0 = __expf(m0 - mn0), sc1 = __expf(m1 - mn1);

        float rs0 = 0.0f, rs1 = 0.0f;
        #pragma unroll
        for (int nf = 0; nf < 8; nf++) {
            s[nf][0] = __expf(s[nf][0] - mn0);
            s[nf][1] = __expf(s[nf][1] - mn0);
            s[nf][2] = __expf(s[nf][2] - mn1);
            s[nf][3] = __expf(s[nf][3] - mn1);
            rs0 += s[nf][0] + s[nf][1];
            rs1 += s[nf][2] + s[nf][3];
        }
        rs0 += __shfl_xor_sync(0xffffffffu, rs0, 1);
        rs0 += __shfl_xor_sync(0xffffffffu, rs0, 2);
        rs1 += __shfl_xor_sync(0xffffffffu, rs1, 1);
        rs1 += __shfl_xor_sync(0xffffffffu, rs1, 2);

        l0 = l0 * sc0 + rs0;
        l1 = l1 * sc1 + rs1;
        m0 = mn0; m1 = mn1;

        #pragma unroll
        for (int nf = 0; nf < 8; nf++) {
            o[nf][0] *= sc0; o[nf][1] *= sc0;
            o[nf][2] *= sc1; o[nf][3] *= sc1;
        }

        #pragma unroll
        for (int nf = 0; nf < 8; nf++) {
            const int c = nf * 8 + 2 * t;
            *(uint2*)(&Ps[prow0 + c]) = make_uint2(f2tf(s[nf][0]), f2tf(s[nf][1]));
            *(uint2*)(&Ps[prow1 + c]) = make_uint2(f2tf(s[nf][2]), f2tf(s[nf][3]));
        }
        __syncwarp();

        #pragma unroll
        for (int ks = 0; ks < 8; ks++) {
            const int c = ks * 8 + t;
            const uint32_t a0 = __float_as_uint(Ps[prow0 + c]);
            const uint32_t a1 = __float_as_uint(Ps[prow1 + c]);
            const uint32_t a2 = __float_as_uint(Ps[prow0 + c + 4]);
            const uint32_t a3 = __float_as_uint(Ps[prow1 + c + 4]);
            #pragma unroll
            for (int nf = 0; nf < 8; nf++) {
                const uint32_t b0 = __float_as_uint(Vs[(c)     * FLD + nf * 8 + g]);
                const uint32_t b1 = __float_as_uint(Vs[(c + 4) * FLD + nf * 8 + g]);
                mma_tf32(o[nf], a0, a1, a2, a3, b0, b1);
            }
        }
        __syncthreads();
    }

    const float inv0 = 1.0f / l0, inv1 = 1.0f / l1;
    const int orow0 = b * Sn + qt * 64 + warp * 16 + g;
    #pragma unroll
    for (int nf = 0; nf < 8; nf++) {
        const int col = h * DKn + nf * 8 + 2 * t;
        *(__half2*)(&O[(size_t)orow0 * Dn + col]) =
            __float22half2_rn(make_float2(o[nf][0] * inv0, o[nf][1] * inv0));
        *(__half2*)(&O[(size_t)(orow0 + 8) * Dn + col]) =
            __float22half2_rn(make_float2(o[nf][2] * inv1, o[nf][3] * inv1));
    }
}

// ============================================================================
// LayerNorm over rows of 1024. One block (256 thr) per row, two-pass.
// Writes f32 out and optionally an fp16 copy (next GEMM's A input).
// ============================================================================
__global__ __launch_bounds__(256)
void layernorm_kernel(const float* __restrict__ in, const float* __restrict__ gamma,
                      const float* __restrict__ beta, float* __restrict__ out,
                      __half* __restrict__ hout)
{
    __shared__ float sb[9];
    const int row = blockIdx.x;
    const int tid = threadIdx.x;
    const float4 xv = *(const float4*)(in + (size_t)row * Dn + tid * 4);

    float ssum = xv.x + xv.y + xv.z + xv.w;
    #pragma unroll
    for (int off = 16; off; off >>= 1) ssum += __shfl_xor_sync(0xffffffffu, ssum, off);
    if ((tid & 31) == 0) sb[tid >> 5] = ssum;
    __syncthreads();
    if (tid == 0) {
        float s = 0.0f;
        #pragma unroll
        for (int i = 0; i < 8; i++) s += sb[i];
        sb[8] = s;
    }
    __syncthreads();
    const float mu = sb[8] * (1.0f / Dn);

    const float d0 = xv.x - mu, d1 = xv.y - mu, d2 = xv.z - mu, d3 = xv.w - mu;
    float sq = d0 * d0 + d1 * d1 + d2 * d2 + d3 * d3;
    __syncthreads();
    #pragma unroll
    for (int off = 16; off; off >>= 1) sq += __shfl_xor_sync(0xffffffffu, sq, off);
    if ((tid & 31) == 0) sb[tid >> 5] = sq;
    __syncthreads();
    if (tid == 0) {
        float s = 0.0f;
        #pragma unroll
        for (int i = 0; i < 8; i++) s += sb[i];
        sb[8] = s;
    }
    __syncthreads();
    const float inv = rsqrtf(sb[8] * (1.0f / Dn) + 1e-5f);

    const float4 gv = *(const float4*)(gamma + tid * 4);
    const float4 bv = *(const float4*)(beta + tid * 4);
    float4 ov;
    ov.x = d0 * inv * gv.x + bv.x;
    ov.y = d1 * inv * gv.y + bv.y;
    ov.z = d2 * inv * gv.z + bv.z;
    ov.w = d3 * inv * gv.w + bv.w;
    *(float4*)(out + (size_t)row * Dn + tid * 4) = ov;
    if (hout) {
        __half2 h0 = __float22half2_rn(make_float2(ov.x, ov.y));
        __half2 h1 = __float22half2_rn(make_float2(ov.z, ov.w));
        *(__half2*)(&hout[(size_t)row * Dn + tid * 4])     = h0;
        *(__half2*)(&hout[(size_t)row * Dn + tid * 4 + 2]) = h1;
    }
}

} // namespace enc

// ============================================================================
// kernel_launch
// ============================================================================
extern "C" void kernel_launch(void* const* d_in, const int* in_sizes, int n_in,
                              void* d_out, int out_size)
{
    using namespace enc;
    (void)in_sizes; (void)n_in; (void)out_size;

    const float* x    = (const float*)d_in[0];
    const float* mask = (const float*)d_in[1];
    const float* Wq   = (const float*)d_in[2];
    const float* bq   = (const float*)d_in[3];
    const float* Wk   = (const float*)d_in[4];
    const float* bk   = (const float*)d_in[5];
    const float* Wv   = (const float*)d_in[6];
    const float* bv   = (const float*)d_in[7];
    const float* Wo   = (const float*)d_in[8];
    const float* bo   = (const float*)d_in[9];
    const float* W1   = (const float*)d_in[10];
    const float* b1   = (const float*)d_in[11];
    const float* W2   = (const float*)d_in[12];
    const float* b2   = (const float*)d_in[13];
    const float* g1   = (const float*)d_in[14];
    const float* be1  = (const float*)d_in[15];
    const float* g2   = (const float*)d_in[16];
    const float* be2  = (const float*)d_in[17];
    float* out = (float*)d_out;

    float  *q, *k, *v, *r, *x1;
    __half *oh, *x1h, *xh, *hh, *wq, *wk, *wv, *wo, *w1, *w2;
    cudaGetSymbolAddress((void**)&q,   g_q);
    cudaGetSymbolAddress((void**)&k,   g_k);
    cudaGetSymbolAddress((void**)&v,   g_v);
    cudaGetSymbolAddress((void**)&r,   g_r);
    cudaGetSymbolAddress((void**)&x1,  g_x1);
    cudaGetSymbolAddress((void**)&oh,  g_oh);
    cudaGetSymbolAddress((void**)&x1h, g_x1h);
    cudaGetSymbolAddress((void**)&xh,  g_xh);
    cudaGetSymbolAddress((void**)&hh,  g_hh);
    cudaGetSymbolAddress((void**)&wq,  g_wq);
    cudaGetSymbolAddress((void**)&wk,  g_wk);
    cudaGetSymbolAddress((void**)&wv,  g_wv);
    cudaGetSymbolAddress((void**)&wo,  g_wo);
    cudaGetSymbolAddress((void**)&w1,  g_w1);
    cudaGetSymbolAddress((void**)&w2,  g_w2);

    cudaFuncSetAttribute(gemm_qkv_kernel,
                         cudaFuncAttributeMaxDynamicSharedMemorySize, GEMM_SMEM);
    cudaFuncSetAttribute(gemm_kernel<false, true, false, true, false>,
                         cudaFuncAttributeMaxDynamicSharedMemorySize, GEMM_SMEM);
    cudaFuncSetAttribute(gemm_kernel<true, false, false, false, true>,
                         cudaFuncAttributeMaxDynamicSharedMemorySize, GEMM_SMEM);
    cudaFuncSetAttribute(flash_kernel,
                         cudaFuncAttributeMaxDynamicSharedMemorySize, FLASH_SMEM);

    // 0: one fused conversion launch (weights + x -> fp16)
    convert_all_kernel<<<(CN_TOTAL + 255) / 256, 256>>>(
        Wq, Wk, Wv, Wo, W1, W2, x, wq, wk, wv, wo, w1, w2, xh);

    const dim3 gQKV(24, 64);
    const dim3 gD(Dn / 128, Mn / 128);
    const dim3 gF(DFFn / 128, Mn / 128);

    // 1: fused QKV (fp16 GEMM, outputs tf32-rounded f32 for flash)
    gemm_qkv_kernel<<<gQKV, 256, GEMM_SMEM>>>(xh, wq, bq, wk, bk, wv, bv, q, k, v);

    // 2: attention (tf32; output fp16)
    flash_kernel<<<dim3(Sn / 64, Hn, Bn), 128, FLASH_SMEM>>>(q, k, v, mask, oh);

    // 3: O-proj + residual(x) -> r (f32)
    gemm_kernel<false, true, false, true, false><<<gD, 256, GEMM_SMEM>>>(
        oh, wo, bo, x, r, nullptr, Dn, Dn);

    // 4: LN1 -> x1 (f32) + x1h (fp16)
    layernorm_kernel<<<Mn, 256>>>(r, g1, be1, x1, x1h);

    // 5: FF1 (relu) -> hh (fp16)   [ncu -s 5 lands here]
    gemm_kernel<true, false, false, false, true><<<gF, 256, GEMM_SMEM>>>(
        x1h, w1, b1, nullptr, nullptr, hh, DFFn, Dn);

    // 6: FF2 + residual(x1) -> r (f32)
    gemm_kernel<false, true, false, true, false><<<gD, 256, GEMM_SMEM>>>(
        hh, w2, b2, x1, r, nullptr, Dn, DFFn);

    // 7: LN2 -> out
    layernorm_kernel<<<Mn, 256>>>(r, g2, be2, out, nullptr);
}

// round 7
// speedup vs baseline: 1.8298x; 1.1120x over previous
#include <cuda_runtime.h>
#include <cuda_fp16.h>
#include <cstdint>

// ============================================================================
// EncoderLayer: x -> MHA(+resid,LN) -> FFN(+resid,LN)
// B=4, S=2048, D=1024, H=16, dk=64, FF=4096.
// R7: fp16 GEMM inner loop rebuilt on ldmatrix.x4 (6 LDSM per k16-step vs 24
//     scalar LDS), BK=64 with 3-stage cp.async (half the syncs). Flash tf32
//     unchanged.
// ============================================================================

namespace enc {

constexpr int Bn   = 4;
constexpr int Sn   = 2048;
constexpr int Dn   = 1024;
constexpr int Hn   = 16;
constexpr int DKn  = 64;
constexpr int DFFn = 4096;
constexpr int Mn   = Bn * Sn;

// Scratch (device globals; no cudaMalloc allowed)
__device__ float  g_q  [Mn * Dn];
__device__ float  g_k  [Mn * Dn];
__device__ float  g_v  [Mn * Dn];
__device__ float  g_r  [Mn * Dn];
__device__ float  g_x1 [Mn * Dn];
__device__ __half g_oh [Mn * Dn];
__device__ __half g_x1h[Mn * Dn];
__device__ __half g_xh [Mn * Dn];
__device__ __half g_hh [Mn * DFFn];
__device__ __half g_wq [Dn * Dn];
__device__ __half g_wk [Dn * Dn];
__device__ __half g_wv [Dn * Dn];
__device__ __half g_wo [Dn * Dn];
__device__ __half g_w1 [DFFn * Dn];
__device__ __half g_w2 [Dn * DFFn];

__device__ __forceinline__ uint32_t f2tf(float f) {
    uint32_t r;
    asm("cvt.rna.tf32.f32 %0, %1;" : "=r"(r) : "f"(f));
    return r;
}
__device__ __forceinline__ float roundtf(float f) {
    return __uint_as_float(f2tf(f));
}

__device__ __forceinline__ void mma_tf32(float c[4],
    uint32_t a0, uint32_t a1, uint32_t a2, uint32_t a3,
    uint32_t b0, uint32_t b1)
{
    asm volatile(
        "mma.sync.aligned.m16n8k8.row.col.f32.tf32.tf32.f32 "
        "{%0,%1,%2,%3}, {%4,%5,%6,%7}, {%8,%9}, {%0,%1,%2,%3};"
        : "+f"(c[0]), "+f"(c[1]), "+f"(c[2]), "+f"(c[3])
        : "r"(a0), "r"(a1), "r"(a2), "r"(a3), "r"(b0), "r"(b1));
}

__device__ __forceinline__ void mma_f16(float c[4],
    uint32_t a0, uint32_t a1, uint32_t a2, uint32_t a3,
    uint32_t b0, uint32_t b1)
{
    asm volatile(
        "mma.sync.aligned.m16n8k16.row.col.f32.f16.f16.f32 "
        "{%0,%1,%2,%3}, {%4,%5,%6,%7}, {%8,%9}, {%0,%1,%2,%3};"
        : "+f"(c[0]), "+f"(c[1]), "+f"(c[2]), "+f"(c[3])
        : "r"(a0), "r"(a1), "r"(a2), "r"(a3), "r"(b0), "r"(b1));
}

__device__ __forceinline__ void ldsm_x4(uint32_t& d0, uint32_t& d1,
                                        uint32_t& d2, uint32_t& d3, uint32_t addr)
{
    asm volatile("ldmatrix.sync.aligned.m8n8.x4.shared.b16 {%0,%1,%2,%3}, [%4];"
                 : "=r"(d0), "=r"(d1), "=r"(d2), "=r"(d3) : "r"(addr));
}

__device__ __forceinline__ void cp16(void* smem_dst, const void* gsrc) {
    uint32_t sa = (uint32_t)__cvta_generic_to_shared(smem_dst);
    asm volatile("cp.async.cg.shared.global [%0], [%1], 16;\n"
                 :: "r"(sa), "l"(gsrc));
}
__device__ __forceinline__ void cp_commit() {
    asm volatile("cp.async.commit_group;\n");
}
template<int N>
__device__ __forceinline__ void cp_wait() {
    asm volatile("cp.async.wait_group %0;\n" :: "n"(N));
}

// ============================================================================
// Fused conversion: all 6 weights + x -> fp16, ONE launch.
// ============================================================================
constexpr int CN_D = Dn * Dn / 4;
constexpr int CN_F = DFFn * Dn / 4;
constexpr int CN_X = Mn * Dn / 4;
constexpr int CN_TOTAL = 4 * CN_D + 2 * CN_F + CN_X;

__global__ __launch_bounds__(256)
void convert_all_kernel(const float* __restrict__ Wq, const float* __restrict__ Wk,
                        const float* __restrict__ Wv, const float* __restrict__ Wo,
                        const float* __restrict__ W1, const float* __restrict__ W2,
                        const float* __restrict__ x,
                        __half* wq, __half* wk, __half* wv, __half* wo,
                        __half* w1, __half* w2, __half* xh)
{
    int idx = blockIdx.x * 256 + threadIdx.x;
    if (idx >= CN_TOTAL) return;
    const float* src; __half* dst;
    if      (idx <  CN_D)          { src = Wq; dst = wq; }
    else if ((idx -= CN_D) < CN_D) { src = Wk; dst = wk; }
    else if ((idx -= CN_D) < CN_D) { src = Wv; dst = wv; }
    else if ((idx -= CN_D) < CN_D) { src = Wo; dst = wo; }
    else if ((idx -= CN_D) < CN_F) { src = W1; dst = w1; }
    else if ((idx -= CN_F) < CN_F) { src = W2; dst = w2; }
    else     { idx -= CN_F;          src = x;  dst = xh; }

    const float4 v = ((const float4*)src)[idx];
    __half2 h0 = __float22half2_rn(make_float2(v.x, v.y));
    __half2 h1 = __float22half2_rn(make_float2(v.z, v.w));
    ((__half2*)dst)[idx * 2]     = h0;
    ((__half2*)dst)[idx * 2 + 1] = h1;
}

// ============================================================================
// fp16 GEMM: C tile = A[BM,K] @ W[BN,K]^T + bias (+resid)(+relu)
// BM=BN=128, BK=64 halves, 3-stage cp.async, 256 thr (2x4 warps, 64x32 tiles).
// Fragments via ldmatrix.x4. Output f32 C (opt tf32-round) and/or fp16 Ch.
// ============================================================================
constexpr int GEMM_STAGES = 3;
constexpr int GLDSH   = 72;                 // halves per smem row (64 + 8 pad)
constexpr int G_STAGE = 128 * GLDSH;        // halves per tile-stage
constexpr int GEMM_SMEM = GEMM_STAGES * 2 * G_STAGE * 2;   // 110592 bytes
constexpr int GBK = 64;                     // K halves per stage

template<bool RELU, bool RESID, bool ROUND, bool WF32, bool WHALF>
__device__ __forceinline__ void gemm_body(
    const __half* __restrict__ A, const __half* __restrict__ W,
    const float* __restrict__ bias, const float* __restrict__ resid,
    float* __restrict__ C, __half* __restrict__ Ch,
    int N, int K, int bm, int bn, __half* smem)
{
    __half* As = smem;
    __half* Bs = smem + GEMM_STAGES * G_STAGE;

    const int tid  = threadIdx.x;
    const int warp = tid >> 5, lane = tid & 31;
    const int wm = (warp >> 2) * 64;
    const int wn = (warp & 3) * 32;
    const int g = lane >> 2, t = lane & 3;

    // staging map: 1024 x 16B chunks per matrix per stage; 4 per thread
    int rowS[4], colS[4];
    #pragma unroll
    for (int i = 0; i < 4; i++) {
        const int idx = tid + i * 256;      // 0..1023
        rowS[i] = idx >> 3;
        colS[i] = (idx & 7) * 8;            // halves
    }
    const __half* Ap = A + (size_t)bm * K;
    const __half* Wp = W + (size_t)bn * K;

    // ldmatrix per-thread base addresses (bytes, shared space)
    const uint32_t smem_a = (uint32_t)__cvta_generic_to_shared(As);
    const uint32_t smem_b = (uint32_t)__cvta_generic_to_shared(Bs);
    // A: lanes 0-15 -> rows 0-15 (k+0); lanes 16-31 -> rows 0-15 (k+8)
    const uint32_t aFragBase = smem_a +
        (uint32_t)(((wm + (lane & 15)) * GLDSH + ((lane >> 4) << 3)) * 2);
    // B: +8 n-rows if lane&16; +8 k-cols if lane&8
    const uint32_t bFragBase = smem_b +
        (uint32_t)(((wn + (lane & 7) + ((lane & 16) >> 1)) * GLDSH + (lane & 8)) * 2);

    float acc[4][4][4];
    #pragma unroll
    for (int mf = 0; mf < 4; mf++)
        #pragma unroll
        for (int nf = 0; nf < 4; nf++)
            #pragma unroll
            for (int e = 0; e < 4; e++) acc[mf][nf][e] = 0.0f;

    const int T = K / GBK;

    #pragma unroll
    for (int s = 0; s < GEMM_STAGES - 1; s++) {
        __half* as = As + s * G_STAGE;
        __half* bs = Bs + s * G_STAGE;
        const int k0 = s * GBK;
        #pragma unroll
        for (int i = 0; i < 4; i++) {
            cp16(as + rowS[i] * GLDSH + colS[i], Ap + (size_t)rowS[i] * K + k0 + colS[i]);
            cp16(bs + rowS[i] * GLDSH + colS[i], Wp + (size_t)rowS[i] * K + k0 + colS[i]);
        }
        cp_commit();
    }

    for (int kt = 0; kt < T; kt++) {
        cp_wait<GEMM_STAGES - 2>();
        __syncthreads();

        if (kt + GEMM_STAGES - 1 < T) {
            const int s = (kt + GEMM_STAGES - 1) % GEMM_STAGES;
            __half* as = As + s * G_STAGE;
            __half* bs = Bs + s * G_STAGE;
            const int k0 = (kt + GEMM_STAGES - 1) * GBK;
            #pragma unroll
            for (int i = 0; i < 4; i++) {
                cp16(as + rowS[i] * GLDSH + colS[i], Ap + (size_t)rowS[i] * K + k0 + colS[i]);
                cp16(bs + rowS[i] * GLDSH + colS[i], Wp + (size_t)rowS[i] * K + k0 + colS[i]);
            }
        }
        cp_commit();

        const uint32_t stOff = (uint32_t)((kt % GEMM_STAGES) * G_STAGE * 2);
        const uint32_t aSt = aFragBase + stOff;
        const uint32_t bSt = bFragBase + stOff;

        #pragma unroll
        for (int ks = 0; ks < 4; ks++) {           // 4 x K16 per BK=64
            const uint32_t kOff = ks * 32;         // 16 halves = 32 bytes
            uint32_t af[4][4], bf[4][2];
            #pragma unroll
            for (int mf = 0; mf < 4; mf++)
                ldsm_x4(af[mf][0], af[mf][1], af[mf][2], af[mf][3],
                        aSt + (uint32_t)(mf * 16 * GLDSH * 2) + kOff);
            #pragma unroll
            for (int j = 0; j < 2; j++)
                ldsm_x4(bf[2*j][0], bf[2*j][1], bf[2*j+1][0], bf[2*j+1][1],
                        bSt + (uint32_t)(j * 16 * GLDSH * 2) + kOff);
            #pragma unroll
            for (int mf = 0; mf < 4; mf++)
                #pragma unroll
                for (int nf = 0; nf < 4; nf++)
                    mma_f16(acc[mf][nf], af[mf][0], af[mf][1], af[mf][2], af[mf][3],
                            bf[nf][0], bf[nf][1]);
        }
    }

    // epilogue
    #pragma unroll
    for (int mf = 0; mf < 4; mf++) {
        const int row0 = bm + wm + mf * 16 + g;
        #pragma unroll
        for (int nf = 0; nf < 4; nf++) {
            const int col = bn + wn + nf * 8 + 2 * t;
            const float b0 = bias[col], b1 = bias[col + 1];
            float v0 = acc[mf][nf][0] + b0;
            float v1 = acc[mf][nf][1] + b1;
            float v2 = acc[mf][nf][2] + b0;
            float v3 = acc[mf][nf][3] + b1;
            if (RESID) {
                const float2 r0v = *(const float2*)(resid + (size_t)row0 * N + col);
                const float2 r1v = *(const float2*)(resid + (size_t)(row0 + 8) * N + col);
                v0 += r0v.x; v1 += r0v.y;
                v2 += r1v.x; v3 += r1v.y;
            }
            if (RELU) {
                v0 = fmaxf(v0, 0.0f); v1 = fmaxf(v1, 0.0f);
                v2 = fmaxf(v2, 0.0f); v3 = fmaxf(v3, 0.0f);
            }
            if (WF32) {
                float u0 = v0, u1 = v1, u2 = v2, u3 = v3;
                if (ROUND) {
                    u0 = roundtf(u0); u1 = roundtf(u1);
                    u2 = roundtf(u2); u3 = roundtf(u3);
                }
                *(float2*)(&C[(size_t)row0 * N + col])       = make_float2(u0, u1);
                *(float2*)(&C[(size_t)(row0 + 8) * N + col]) = make_float2(u2, u3);
            }
            if (WHALF) {
                *(__half2*)(&Ch[(size_t)row0 * N + col]) =
                    __float22half2_rn(make_float2(v0, v1));
                *(__half2*)(&Ch[(size_t)(row0 + 8) * N + col]) =
                    __float22half2_rn(make_float2(v2, v3));
            }
        }
    }
}

template<bool RELU, bool RESID, bool ROUND, bool WF32, bool WHALF>
__global__ __launch_bounds__(256, 2)
void gemm_kernel(const __half* __restrict__ A, const __half* __restrict__ W,
                 const float* __restrict__ bias, const float* __restrict__ resid,
                 float* __restrict__ C, __half* __restrict__ Ch, int N, int K)
{
    extern __shared__ __half smem[];
    gemm_body<RELU, RESID, ROUND, WF32, WHALF>(A, W, bias, resid, C, Ch, N, K,
                                               blockIdx.y * 128, blockIdx.x * 128, smem);
}

// Fused QKV: one launch; outputs tf32-rounded f32 (flash inputs)
__global__ __launch_bounds__(256, 2)
void gemm_qkv_kernel(const __half* __restrict__ x,
                     const __half* __restrict__ Wq, const float* __restrict__ bq,
                     const __half* __restrict__ Wk, const float* __restrict__ bk,
                     const __half* __restrict__ Wv, const float* __restrict__ bv,
                     float* __restrict__ q, float* __restrict__ k, float* __restrict__ v)
{
    extern __shared__ __half smem[];
    const int sel = blockIdx.x >> 3;
    const int bx  = blockIdx.x & 7;
    const __half* W = (sel == 0) ? Wq : (sel == 1) ? Wk : Wv;
    const float*  b = (sel == 0) ? bq : (sel == 1) ? bk : bv;
    float*        C = (sel == 0) ? q  : (sel == 1) ? k  : v;
    gemm_body<false, false, true, true, false>(x, W, b, nullptr, C, nullptr, Dn, Dn,
                                               blockIdx.y * 128, bx * 128, smem);
}

// ============================================================================
// Flash attention (tf32, unchanged). CTA = (64 q, head, batch), 128 thr.
// K/V/mask double-buffered via cp.async. Output fp16.
// ============================================================================
constexpr int FLD = 68;
constexpr int F_TILE = 64 * FLD;
constexpr int FLASH_SMEM = (5 * F_TILE + 128) * 4;

__global__ __launch_bounds__(128)
void flash_kernel(const float* __restrict__ Q, const float* __restrict__ Km,
                  const float* __restrict__ V, const float* __restrict__ mask,
                  __half* __restrict__ O)
{
    extern __shared__ float sm[];
    float* Qs = sm;

    const int qt = blockIdx.x, h = blockIdx.y, b = blockIdx.z;
    const int tid = threadIdx.x;
    const int warp = tid >> 5, lane = tid & 31;
    const int g = lane >> 2, t = lane & 3;
    constexpr float SCALE = 0.125f;
    constexpr int T = Sn / 64;

    const float* Kb0 = Km + (size_t)(b * Sn) * Dn + h * DKn;
    const float* Vb0 = V  + (size_t)(b * Sn) * Dn + h * DKn;
    const float* Mb  = mask + b * Sn;

    auto stage = [&](int kt, int buf) {
        const float* Kb = Kb0 + (size_t)kt * 64 * Dn;
        const float* Vb = Vb0 + (size_t)kt * 64 * Dn;
        float* ks = sm + (1 + buf) * F_TILE;
        float* vs = sm + (3 + buf) * F_TILE;
        #pragma unroll
        for (int i = 0; i < 8; i++) {
            const int idx = tid + i * 128;
            const int r = idx >> 4, c4 = (idx & 15) * 4;
            cp16(ks + r * FLD + c4, Kb + (size_t)r * Dn + c4);
            cp16(vs + r * FLD + c4, Vb + (size_t)r * Dn + c4);
        }
        if (tid < 16) cp16(sm + 5 * F_TILE + buf * 64 + tid * 4, Mb + kt * 64 + tid * 4);
    };

    const float* Qb = Q + (size_t)(b * Sn + qt * 64) * Dn + h * DKn;
    for (int i = tid; i < 64 * 16; i += 128) {
        const int r = i >> 4, c4 = (i & 15) * 4;
        *(float4*)(&Qs[r * FLD + c4]) = *(const float4*)(Qb + (size_t)r * Dn + c4);
    }

    stage(0, 0);
    cp_commit();
    __syncthreads();

    const int prow0 = (warp * 16 + g) * FLD;
    const int prow1 = prow0 + 8 * FLD;
    uint32_t aq[8][4];
    #pragma unroll
    for (int ks = 0; ks < 8; ks++) {
        const int c = ks * 8 + t;
        aq[ks][0] = __float_as_uint(Qs[prow0 + c]);
        aq[ks][1] = __float_as_uint(Qs[prow1 + c]);
        aq[ks][2] = __float_as_uint(Qs[prow0 + c + 4]);
        aq[ks][3] = __float_as_uint(Qs[prow1 + c + 4]);
    }
    __syncthreads();
    float* Ps = Qs;

    float m0 = -1e30f, m1 = -1e30f, l0 = 0.0f, l1 = 0.0f;
    float o[8][4];
    #pragma unroll
    for (int nf = 0; nf < 8; nf++)
        #pragma unroll
        for (int e = 0; e < 4; e++) o[nf][e] = 0.0f;

    for (int kt = 0; kt < T; kt++) {
        if (kt + 1 < T) stage(kt + 1, (kt + 1) & 1);
        cp_commit();
        cp_wait<1>();
        __syncthreads();

        const float* Ks = sm + (1 + (kt & 1)) * F_TILE;
        const float* Vs = sm + (3 + (kt & 1)) * F_TILE;
        const float* Ms = sm + 5 * F_TILE + (kt & 1) * 64;

        float s[8][4];
        #pragma unroll
        for (int nf = 0; nf < 8; nf++)
            #pragma unroll
            for (int e = 0; e < 4; e++) s[nf][e] = 0.0f;

        #pragma unroll
        for (int ks = 0; ks < 8; ks++) {
            const int c = ks * 8 + t;
            #pragma unroll
            for (int nf = 0; nf < 8; nf++) {
                const int nr = (nf * 8 + g) * FLD;
                const uint32_t b0 = __float_as_uint(Ks[nr + c]);
                const uint32_t b1 = __float_as_uint(Ks[nr + c + 4]);
                mma_tf32(s[nf], aq[ks][0], aq[ks][1], aq[ks][2], aq[ks][3], b0, b1);
            }
        }

        float rmax0 = -1e30f, rmax1 = -1e30f;
        #pragma unroll
        for (int nf = 0; nf < 8; nf++) {
            const float mk0 = Ms[nf * 8 + 2 * t];
            const float mk1 = Ms[nf * 8 + 2 * t + 1];
            s[nf][0] = s[nf][0] * SCALE + mk0;
            s[nf][1] = s[nf][1] * SCALE + mk1;
            s[nf][2] = s[nf][2] * SCALE + mk0;
            s[nf][3] = s[nf][3] * SCALE + mk1;
            rmax0 = fmaxf(rmax0, fmaxf(s[nf][0], s[nf][1]));
            rmax1 = fmaxf(rmax1, fmaxf(s[nf][2], s[nf][3]));
        }
        rmax0 = fmaxf(rmax0, __shfl_xor_sync(0xffffffffu, rmax0, 1));
        rmax0 = fmaxf(rmax0, __shfl_xor_sync(0xffffffffu, rmax0, 2));
        rmax1 = fmaxf(rmax1, __shfl_xor_sync(0xffffffffu, rmax1, 1));
        rmax1 = fmaxf(rmax1, __shfl_xor_sync(0xffffffffu, rmax1, 2));

        const float mn0 = fmaxf(m0, rmax0), mn1 = fmaxf(m1, rmax1);
        const float sc0 = __expf(m0 - mn0), sc1 = __expf(m1 - mn1);

        float rs0 = 0.0f, rs1 = 0.0f;
        #pragma unroll
        for (int nf = 0; nf < 8; nf++) {
            s[nf][0] = __expf(s[nf][0] - mn0);
            s[nf][1] = __expf(s[nf][1] - mn0);
            s[nf][2] = __expf(s[nf][2] - mn1);
            s[nf][3] = __expf(s[nf][3] - mn1);
            rs0 += s[nf][0] + s[nf][1];
            rs1 += s[nf][2] + s[nf][3];
        }
        rs0 += __shfl_xor_sync(0xffffffffu, rs0, 1);
        rs0 += __shfl_xor_sync(0xffffffffu, rs0, 2);
        rs1 += __shfl_xor_sync(0xffffffffu, rs1, 1);
        rs1 += __shfl_xor_sync(0xffffffffu, rs1, 2);

        l0 = l0 * sc0 + rs0;
        l1 = l1 * sc1 + rs1;
        m0 = mn0; m1 = mn1;

        #pragma unroll
        for (int nf = 0; nf < 8; nf++) {
            o[nf][0] *= sc0; o[nf][1] *= sc0;
            o[nf][2] *= sc1; o[nf][3] *= sc1;
        }

        #pragma unroll
        for (int nf = 0; nf < 8; nf++) {
            const int c = nf * 8 + 2 * t;
            *(uint2*)(&Ps[prow0 + c]) = make_uint2(f2tf(s[nf][0]), f2tf(s[nf][1]));
            *(uint2*)(&Ps[prow1 + c]) = make_uint2(f2tf(s[nf][2]), f2tf(s[nf][3]));
        }
        __syncwarp();

        #pragma unroll
        for (int ks = 0; ks < 8; ks++) {
            const int c = ks * 8 + t;
            const uint32_t a0 = __float_as_uint(Ps[prow0 + c]);
            const uint32_t a1 = __float_as_uint(Ps[prow1 + c]);
            const uint32_t a2 = __float_as_uint(Ps[prow0 + c + 4]);
            const uint32_t a3 = __float_as_uint(Ps[prow1 + c + 4]);
            #pragma unroll
            for (int nf = 0; nf < 8; nf++) {
                const uint32_t b0 = __float_as_uint(Vs[(c)     * FLD + nf * 8 + g]);
                const uint32_t b1 = __float_as_uint(Vs[(c + 4) * FLD + nf * 8 + g]);
                mma_tf32(o[nf], a0, a1, a2, a3, b0, b1);
            }
        }
        __syncthreads();
    }

    const float inv0 = 1.0f / l0, inv1 = 1.0f / l1;
    const int orow0 = b * Sn + qt * 64 + warp * 16 + g;
    #pragma unroll
    for (int nf = 0; nf < 8; nf++) {
        const int col = h * DKn + nf * 8 + 2 * t;
        *(__half2*)(&O[(size_t)orow0 * Dn + col]) =
            __float22half2_rn(make_float2(o[nf][0] * inv0, o[nf][1] * inv0));
        *(__half2*)(&O[(size_t)(orow0 + 8) * Dn + col]) =
            __float22half2_rn(make_float2(o[nf][2] * inv1, o[nf][3] * inv1));
    }
}

// ============================================================================
// LayerNorm over rows of 1024. One block (256 thr) per row, two-pass.
// ============================================================================
__global__ __launch_bounds__(256)
void layernorm_kernel(const float* __restrict__ in, const float* __restrict__ gamma,
                      const float* __restrict__ beta, float* __restrict__ out,
                      __half* __restrict__ hout)
{
    __shared__ float sb[9];
    const int row = blockIdx.x;
    const int tid = threadIdx.x;
    const float4 xv = *(const float4*)(in + (size_t)row * Dn + tid * 4);

    float ssum = xv.x + xv.y + xv.z + xv.w;
    #pragma unroll
    for (int off = 16; off; off >>= 1) ssum += __shfl_xor_sync(0xffffffffu, ssum, off);
    if ((tid & 31) == 0) sb[tid >> 5] = ssum;
    __syncthreads();
    if (tid == 0) {
        float s = 0.0f;
        #pragma unroll
        for (int i = 0; i < 8; i++) s += sb[i];
        sb[8] = s;
    }
    __syncthreads();
    const float mu = sb[8] * (1.0f / Dn);

    const float d0 = xv.x - mu, d1 = xv.y - mu, d2 = xv.z - mu, d3 = xv.w - mu;
    float sq = d0 * d0 + d1 * d1 + d2 * d2 + d3 * d3;
    __syncthreads();
    #pragma unroll
    for (int off = 16; off; off >>= 1) sq += __shfl_xor_sync(0xffffffffu, sq, off);
    if ((tid & 31) == 0) sb[tid >> 5] = sq;
    __syncthreads();
    if (tid == 0) {
        float s = 0.0f;
        #pragma unroll
        for (int i = 0; i < 8; i++) s += sb[i];
        sb[8] = s;
    }
    __syncthreads();
    const float inv = rsqrtf(sb[8] * (1.0f / Dn) + 1e-5f);

    const float4 gv = *(const float4*)(gamma + tid * 4);
    const float4 bv = *(const float4*)(beta + tid * 4);
    float4 ov;
    ov.x = d0 * inv * gv.x + bv.x;
    ov.y = d1 * inv * gv.y + bv.y;
    ov.z = d2 * inv * gv.z + bv.z;
    ov.w = d3 * inv * gv.w + bv.w;
    *(float4*)(out + (size_t)row * Dn + tid * 4) = ov;
    if (hout) {
        __half2 h0 = __float22half2_rn(make_float2(ov.x, ov.y));
        __half2 h1 = __float22half2_rn(make_float2(ov.z, ov.w));
        *(__half2*)(&hout[(size_t)row * Dn + tid * 4])     = h0;
        *(__half2*)(&hout[(size_t)row * Dn + tid * 4 + 2]) = h1;
    }
}

} // namespace enc

// ============================================================================
// kernel_launch
// ============================================================================
extern "C" void kernel_launch(void* const* d_in, const int* in_sizes, int n_in,
                              void* d_out, int out_size)
{
    using namespace enc;
    (void)in_sizes; (void)n_in; (void)out_size;

    const float* x    = (const float*)d_in[0];
    const float* mask = (const float*)d_in[1];
    const float* Wq   = (const float*)d_in[2];
    const float* bq   = (const float*)d_in[3];
    const float* Wk   = (const float*)d_in[4];
    const float* bk   = (const float*)d_in[5];
    const float* Wv   = (const float*)d_in[6];
    const float* bv   = (const float*)d_in[7];
    const float* Wo   = (const float*)d_in[8];
    const float* bo   = (const float*)d_in[9];
    const float* W1   = (const float*)d_in[10];
    const float* b1   = (const float*)d_in[11];
    const float* W2   = (const float*)d_in[12];
    const float* b2   = (const float*)d_in[13];
    const float* g1   = (const float*)d_in[14];
    const float* be1  = (const float*)d_in[15];
    const float* g2   = (const float*)d_in[16];
    const float* be2  = (const float*)d_in[17];
    float* out = (float*)d_out;

    float  *q, *k, *v, *r, *x1;
    __half *oh, *x1h, *xh, *hh, *wq, *wk, *wv, *wo, *w1, *w2;
    cudaGetSymbolAddress((void**)&q,   g_q);
    cudaGetSymbolAddress((void**)&k,   g_k);
    cudaGetSymbolAddress((void**)&v,   g_v);
    cudaGetSymbolAddress((void**)&r,   g_r);
    cudaGetSymbolAddress((void**)&x1,  g_x1);
    cudaGetSymbolAddress((void**)&oh,  g_oh);
    cudaGetSymbolAddress((void**)&x1h, g_x1h);
    cudaGetSymbolAddress((void**)&xh,  g_xh);
    cudaGetSymbolAddress((void**)&hh,  g_hh);
    cudaGetSymbolAddress((void**)&wq,  g_wq);
    cudaGetSymbolAddress((void**)&wk,  g_wk);
    cudaGetSymbolAddress((void**)&wv,  g_wv);
    cudaGetSymbolAddress((void**)&wo,  g_wo);
    cudaGetSymbolAddress((void**)&w1,  g_w1);
    cudaGetSymbolAddress((void**)&w2,  g_w2);

    cudaFuncSetAttribute(gemm_qkv_kernel,
                         cudaFuncAttributeMaxDynamicSharedMemorySize, GEMM_SMEM);
    cudaFuncSetAttribute(gemm_kernel<false, true, false, true, false>,
                         cudaFuncAttributeMaxDynamicSharedMemorySize, GEMM_SMEM);
    cudaFuncSetAttribute(gemm_kernel<true, false, false, false, true>,
                         cudaFuncAttributeMaxDynamicSharedMemorySize, GEMM_SMEM);
    cudaFuncSetAttribute(flash_kernel,
                         cudaFuncAttributeMaxDynamicSharedMemorySize, FLASH_SMEM);

    // 0: one fused conversion launch (weights + x -> fp16)
    convert_all_kernel<<<(CN_TOTAL + 255) / 256, 256>>>(
        Wq, Wk, Wv, Wo, W1, W2, x, wq, wk, wv, wo, w1, w2, xh);

    const dim3 gQKV(24, 64);
    const dim3 gD(Dn / 128, Mn / 128);
    const dim3 gF(DFFn / 128, Mn / 128);

    // 1: fused QKV (fp16 GEMM, outputs tf32-rounded f32 for flash)
    gemm_qkv_kernel<<<gQKV, 256, GEMM_SMEM>>>(xh, wq, bq, wk, bk, wv, bv, q, k, v);

    // 2: attention (tf32; output fp16)
    flash_kernel<<<dim3(Sn / 64, Hn, Bn), 128, FLASH_SMEM>>>(q, k, v, mask, oh);

    // 3: O-proj + residual(x) -> r (f32)
    gemm_kernel<false, true, false, true, false><<<gD, 256, GEMM_SMEM>>>(
        oh, wo, bo, x, r, nullptr, Dn, Dn);

    // 4: LN1 -> x1 (f32) + x1h (fp16)
    layernorm_kernel<<<Mn, 256>>>(r, g1, be1, x1, x1h);

    // 5: FF1 (relu) -> hh (fp16)   [ncu -s 5 lands here]
    gemm_kernel<true, false, false, false, true><<<gF, 256, GEMM_SMEM>>>(
        x1h, w1, b1, nullptr, nullptr, hh, DFFn, Dn);

    // 6: FF2 + residual(x1) -> r (f32)
    gemm_kernel<false, true, false, true, false><<<gD, 256, GEMM_SMEM>>>(
        hh, w2, b2, x1, r, nullptr, Dn, DFFn);

    // 7: LN2 -> out
    layernorm_kernel<<<Mn, 256>>>(r, g2, be2, out, nullptr);
}

// round 9
// speedup vs baseline: 2.6312x; 1.4380x over previous
#include <cuda_runtime.h>
#include <cuda_fp16.h>
#include <cstdint>

// ============================================================================
// EncoderLayer: x -> MHA(+resid,LN) -> FFN(+resid,LN)
// B=4, S=2048, D=1024, H=16, dk=64, FF=4096.
// R9 (= R8 with packh2 compile fix): flash attention in fp16 (m16n8k16):
//     fp16 K/V tiles (half the smem), ldmatrix feeds, P kept entirely in
//     registers (C-frag -> A-frag identity), V via ldmatrix.trans, 4 CTAs/SM.
//     GEMMs unchanged from R7.
// ============================================================================

namespace enc {

constexpr int Bn   = 4;
constexpr int Sn   = 2048;
constexpr int Dn   = 1024;
constexpr int Hn   = 16;
constexpr int DKn  = 64;
constexpr int DFFn = 4096;
constexpr int Mn   = Bn * Sn;

// Scratch (device globals; no cudaMalloc allowed)
__device__ float  g_r  [Mn * Dn];
__device__ float  g_x1 [Mn * Dn];
__device__ __half g_qh [Mn * Dn];
__device__ __half g_kh [Mn * Dn];
__device__ __half g_vh [Mn * Dn];
__device__ __half g_oh [Mn * Dn];
__device__ __half g_x1h[Mn * Dn];
__device__ __half g_xh [Mn * Dn];
__device__ __half g_hh [Mn * DFFn];
__device__ __half g_wq [Dn * Dn];
__device__ __half g_wk [Dn * Dn];
__device__ __half g_wv [Dn * Dn];
__device__ __half g_wo [Dn * Dn];
__device__ __half g_w1 [DFFn * Dn];
__device__ __half g_w2 [Dn * DFFn];

__device__ __forceinline__ void mma_f16(float c[4],
    uint32_t a0, uint32_t a1, uint32_t a2, uint32_t a3,
    uint32_t b0, uint32_t b1)
{
    asm volatile(
        "mma.sync.aligned.m16n8k16.row.col.f32.f16.f16.f32 "
        "{%0,%1,%2,%3}, {%4,%5,%6,%7}, {%8,%9}, {%0,%1,%2,%3};"
        : "+f"(c[0]), "+f"(c[1]), "+f"(c[2]), "+f"(c[3])
        : "r"(a0), "r"(a1), "r"(a2), "r"(a3), "r"(b0), "r"(b1));
}

__device__ __forceinline__ void ldsm_x4(uint32_t& d0, uint32_t& d1,
                                        uint32_t& d2, uint32_t& d3, uint32_t addr)
{
    asm volatile("ldmatrix.sync.aligned.m8n8.x4.shared.b16 {%0,%1,%2,%3}, [%4];"
                 : "=r"(d0), "=r"(d1), "=r"(d2), "=r"(d3) : "r"(addr));
}
__device__ __forceinline__ void ldsm_x4_trans(uint32_t& d0, uint32_t& d1,
                                              uint32_t& d2, uint32_t& d3, uint32_t addr)
{
    asm volatile("ldmatrix.sync.aligned.m8n8.x4.trans.shared.b16 {%0,%1,%2,%3}, [%4];"
                 : "=r"(d0), "=r"(d1), "=r"(d2), "=r"(d3) : "r"(addr));
}

// pack two f32 -> f16x2: element0 (lo) = a, element1 (hi) = b
__device__ __forceinline__ uint32_t packh2(float a, float b) {
    uint32_t r;
    asm("cvt.rn.f16x2.f32 %0, %1, %2;" : "=r"(r) : "f"(b), "f"(a));
    return r;
}

__device__ __forceinline__ void cp16(void* smem_dst, const void* gsrc) {
    uint32_t sa = (uint32_t)__cvta_generic_to_shared(smem_dst);
    asm volatile("cp.async.cg.shared.global [%0], [%1], 16;\n"
                 :: "r"(sa), "l"(gsrc));
}
__device__ __forceinline__ void cp_commit() {
    asm volatile("cp.async.commit_group;\n");
}
template<int N>
__device__ __forceinline__ void cp_wait() {
    asm volatile("cp.async.wait_group %0;\n" :: "n"(N));
}

// ============================================================================
// Fused conversion: all 6 weights + x -> fp16, ONE launch.
// ============================================================================
constexpr int CN_D = Dn * Dn / 4;
constexpr int CN_F = DFFn * Dn / 4;
constexpr int CN_X = Mn * Dn / 4;
constexpr int CN_TOTAL = 4 * CN_D + 2 * CN_F + CN_X;

__global__ __launch_bounds__(256)
void convert_all_kernel(const float* __restrict__ Wq, const float* __restrict__ Wk,
                        const float* __restrict__ Wv, const float* __restrict__ Wo,
                        const float* __restrict__ W1, const float* __restrict__ W2,
                        const float* __restrict__ x,
                        __half* wq, __half* wk, __half* wv, __half* wo,
                        __half* w1, __half* w2, __half* xh)
{
    int idx = blockIdx.x * 256 + threadIdx.x;
    if (idx >= CN_TOTAL) return;
    const float* src; __half* dst;
    if      (idx <  CN_D)          { src = Wq; dst = wq; }
    else if ((idx -= CN_D) < CN_D) { src = Wk; dst = wk; }
    else if ((idx -= CN_D) < CN_D) { src = Wv; dst = wv; }
    else if ((idx -= CN_D) < CN_D) { src = Wo; dst = wo; }
    else if ((idx -= CN_D) < CN_F) { src = W1; dst = w1; }
    else if ((idx -= CN_F) < CN_F) { src = W2; dst = w2; }
    else     { idx -= CN_F;          src = x;  dst = xh; }

    const float4 v = ((const float4*)src)[idx];
    __half2 h0 = __float22half2_rn(make_float2(v.x, v.y));
    __half2 h1 = __float22half2_rn(make_float2(v.z, v.w));
    ((__half2*)dst)[idx * 2]     = h0;
    ((__half2*)dst)[idx * 2 + 1] = h1;
}

// ============================================================================
// fp16 GEMM (unchanged from R7): BM=BN=128, BK=64, 3-stage cp.async, ldmatrix.
// ============================================================================
constexpr int GEMM_STAGES = 3;
constexpr int GLDSH   = 72;
constexpr int G_STAGE = 128 * GLDSH;
constexpr int GEMM_SMEM = GEMM_STAGES * 2 * G_STAGE * 2;
constexpr int GBK = 64;

template<bool RELU, bool RESID, bool WF32, bool WHALF>
__device__ __forceinline__ void gemm_body(
    const __half* __restrict__ A, const __half* __restrict__ W,
    const float* __restrict__ bias, const float* __restrict__ resid,
    float* __restrict__ C, __half* __restrict__ Ch,
    int N, int K, int bm, int bn, __half* smem)
{
    __half* As = smem;
    __half* Bs = smem + GEMM_STAGES * G_STAGE;

    const int tid  = threadIdx.x;
    const int warp = tid >> 5, lane = tid & 31;
    const int wm = (warp >> 2) * 64;
    const int wn = (warp & 3) * 32;
    const int g = lane >> 2, t = lane & 3;

    int rowS[4], colS[4];
    #pragma unroll
    for (int i = 0; i < 4; i++) {
        const int idx = tid + i * 256;
        rowS[i] = idx >> 3;
        colS[i] = (idx & 7) * 8;
    }
    const __half* Ap = A + (size_t)bm * K;
    const __half* Wp = W + (size_t)bn * K;

    const uint32_t smem_a = (uint32_t)__cvta_generic_to_shared(As);
    const uint32_t smem_b = (uint32_t)__cvta_generic_to_shared(Bs);
    const uint32_t aFragBase = smem_a +
        (uint32_t)(((wm + (lane & 15)) * GLDSH + ((lane >> 4) << 3)) * 2);
    const uint32_t bFragBase = smem_b +
        (uint32_t)(((wn + (lane & 7) + ((lane & 16) >> 1)) * GLDSH + (lane & 8)) * 2);

    float acc[4][4][4];
    #pragma unroll
    for (int mf = 0; mf < 4; mf++)
        #pragma unroll
        for (int nf = 0; nf < 4; nf++)
            #pragma unroll
            for (int e = 0; e < 4; e++) acc[mf][nf][e] = 0.0f;

    const int T = K / GBK;

    #pragma unroll
    for (int s = 0; s < GEMM_STAGES - 1; s++) {
        __half* as = As + s * G_STAGE;
        __half* bs = Bs + s * G_STAGE;
        const int k0 = s * GBK;
        #pragma unroll
        for (int i = 0; i < 4; i++) {
            cp16(as + rowS[i] * GLDSH + colS[i], Ap + (size_t)rowS[i] * K + k0 + colS[i]);
            cp16(bs + rowS[i] * GLDSH + colS[i], Wp + (size_t)rowS[i] * K + k0 + colS[i]);
        }
        cp_commit();
    }

    for (int kt = 0; kt < T; kt++) {
        cp_wait<GEMM_STAGES - 2>();
        __syncthreads();

        if (kt + GEMM_STAGES - 1 < T) {
            const int s = (kt + GEMM_STAGES - 1) % GEMM_STAGES;
            __half* as = As + s * G_STAGE;
            __half* bs = Bs + s * G_STAGE;
            const int k0 = (kt + GEMM_STAGES - 1) * GBK;
            #pragma unroll
            for (int i = 0; i < 4; i++) {
                cp16(as + rowS[i] * GLDSH + colS[i], Ap + (size_t)rowS[i] * K + k0 + colS[i]);
                cp16(bs + rowS[i] * GLDSH + colS[i], Wp + (size_t)rowS[i] * K + k0 + colS[i]);
            }
        }
        cp_commit();

        const uint32_t stOff = (uint32_t)((kt % GEMM_STAGES) * G_STAGE * 2);
        const uint32_t aSt = aFragBase + stOff;
        const uint32_t bSt = bFragBase + stOff;

        #pragma unroll
        for (int ks = 0; ks < 4; ks++) {
            const uint32_t kOff = ks * 32;
            uint32_t af[4][4], bf[4][2];
            #pragma unroll
            for (int mf = 0; mf < 4; mf++)
                ldsm_x4(af[mf][0], af[mf][1], af[mf][2], af[mf][3],
                        aSt + (uint32_t)(mf * 16 * GLDSH * 2) + kOff);
            #pragma unroll
            for (int j = 0; j < 2; j++)
                ldsm_x4(bf[2*j][0], bf[2*j][1], bf[2*j+1][0], bf[2*j+1][1],
                        bSt + (uint32_t)(j * 16 * GLDSH * 2) + kOff);
            #pragma unroll
            for (int mf = 0; mf < 4; mf++)
                #pragma unroll
                for (int nf = 0; nf < 4; nf++)
                    mma_f16(acc[mf][nf], af[mf][0], af[mf][1], af[mf][2], af[mf][3],
                            bf[nf][0], bf[nf][1]);
        }
    }

    #pragma unroll
    for (int mf = 0; mf < 4; mf++) {
        const int row0 = bm + wm + mf * 16 + g;
        #pragma unroll
        for (int nf = 0; nf < 4; nf++) {
            const int col = bn + wn + nf * 8 + 2 * t;
            const float b0 = bias[col], b1 = bias[col + 1];
            float v0 = acc[mf][nf][0] + b0;
            float v1 = acc[mf][nf][1] + b1;
            float v2 = acc[mf][nf][2] + b0;
            float v3 = acc[mf][nf][3] + b1;
            if (RESID) {
                const float2 r0v = *(const float2*)(resid + (size_t)row0 * N + col);
                const float2 r1v = *(const float2*)(resid + (size_t)(row0 + 8) * N + col);
                v0 += r0v.x; v1 += r0v.y;
                v2 += r1v.x; v3 += r1v.y;
            }
            if (RELU) {
                v0 = fmaxf(v0, 0.0f); v1 = fmaxf(v1, 0.0f);
                v2 = fmaxf(v2, 0.0f); v3 = fmaxf(v3, 0.0f);
            }
            if (WF32) {
                *(float2*)(&C[(size_t)row0 * N + col])       = make_float2(v0, v1);
                *(float2*)(&C[(size_t)(row0 + 8) * N + col]) = make_float2(v2, v3);
            }
            if (WHALF) {
                *(__half2*)(&Ch[(size_t)row0 * N + col]) =
                    __float22half2_rn(make_float2(v0, v1));
                *(__half2*)(&Ch[(size_t)(row0 + 8) * N + col]) =
                    __float22half2_rn(make_float2(v2, v3));
            }
        }
    }
}

template<bool RELU, bool RESID, bool WF32, bool WHALF>
__global__ __launch_bounds__(256, 2)
void gemm_kernel(const __half* __restrict__ A, const __half* __restrict__ W,
                 const float* __restrict__ bias, const float* __restrict__ resid,
                 float* __restrict__ C, __half* __restrict__ Ch, int N, int K)
{
    extern __shared__ __half smem[];
    gemm_body<RELU, RESID, WF32, WHALF>(A, W, bias, resid, C, Ch, N, K,
                                        blockIdx.y * 128, blockIdx.x * 128, smem);
}

// Fused QKV: one launch; outputs fp16 (flash inputs)
__global__ __launch_bounds__(256, 2)
void gemm_qkv_kernel(const __half* __restrict__ x,
                     const __half* __restrict__ Wq, const float* __restrict__ bq,
                     const __half* __restrict__ Wk, const float* __restrict__ bk,
                     const __half* __restrict__ Wv, const float* __restrict__ bv,
                     __half* __restrict__ q, __half* __restrict__ k, __half* __restrict__ v)
{
    extern __shared__ __half smem[];
    const int sel = blockIdx.x >> 3;
    const int bx  = blockIdx.x & 7;
    const __half* W = (sel == 0) ? Wq : (sel == 1) ? Wk : Wv;
    const float*  b = (sel == 0) ? bq : (sel == 1) ? bk : bv;
    __half*       C = (sel == 0) ? q  : (sel == 1) ? k  : v;
    gemm_body<false, false, false, true>(x, W, b, nullptr, nullptr, C, Dn, Dn,
                                         blockIdx.y * 128, bx * 128, smem);
}

// ============================================================================
// Flash attention, fp16 MMA. CTA = (64 q-rows, head, batch), 128 thr.
// Q/K/V fp16; K/V/mask double-buffered cp.async; P stays in registers.
// ============================================================================
constexpr int FLDH   = 72;                       // halves per tile row (64+8)
constexpr int FT     = 64 * FLDH;                // halves per tile (4608)
constexpr int FLASH_SMEM = (5 * FT) * 2 + 2 * 64 * 4;   // Q + K[2] + V[2] + Ms[2]

__global__ __launch_bounds__(128, 4)
void flash_kernel(const __half* __restrict__ Q, const __half* __restrict__ Km,
                  const __half* __restrict__ V, const float* __restrict__ mask,
                  __half* __restrict__ O)
{
    extern __shared__ __half smh[];
    __half* Qs = smh;                  // [64][72]
    __half* Ks = smh + FT;             // [2][64][72]
    __half* Vs = smh + 3 * FT;         // [2][64][72]
    float*  Ms = (float*)(smh + 5 * FT);   // [2][64]

    const int qt = blockIdx.x, h = blockIdx.y, b = blockIdx.z;
    const int tid = threadIdx.x;
    const int warp = tid >> 5, lane = tid & 31;
    const int g = lane >> 2, t = lane & 3;
    constexpr float SCALE = 0.125f;
    constexpr int T = Sn / 64;

    const __half* Kb0 = Km + (size_t)(b * Sn) * Dn + h * DKn;
    const __half* Vb0 = V  + (size_t)(b * Sn) * Dn + h * DKn;
    const float*  Mb  = mask + b * Sn;

    auto stage = [&](int kt, int buf) {
        const __half* Kb = Kb0 + (size_t)kt * 64 * Dn;
        const __half* Vb = Vb0 + (size_t)kt * 64 * Dn;
        __half* ks = Ks + buf * FT;
        __half* vs = Vs + buf * FT;
        #pragma unroll
        for (int i = 0; i < 4; i++) {
            const int idx = tid + i * 128;           // 0..511 chunks
            const int r = idx >> 3, c8 = (idx & 7) * 8;
            cp16(ks + r * FLDH + c8, Kb + (size_t)r * Dn + c8);
            cp16(vs + r * FLDH + c8, Vb + (size_t)r * Dn + c8);
        }
        if (tid < 16) cp16(Ms + buf * 64 + tid * 4, Mb + kt * 64 + tid * 4);
    };

    // load Q tile (fp16) via cp.async
    {
        const __half* Qb = Q + (size_t)(b * Sn + qt * 64) * Dn + h * DKn;
        #pragma unroll
        for (int i = 0; i < 4; i++) {
            const int idx = tid + i * 128;
            const int r = idx >> 3, c8 = (idx & 7) * 8;
            cp16(Qs + r * FLDH + c8, Qb + (size_t)r * Dn + c8);
        }
    }
    stage(0, 0);
    cp_commit();
    cp_wait<0>();
    __syncthreads();

    // hoist Q fragments: warp owns rows warp*16..+15; 4 k16 tiles
    const uint32_t qsm = (uint32_t)__cvta_generic_to_shared(Qs);
    const uint32_t aQBase = qsm +
        (uint32_t)(((warp * 16 + (lane & 15)) * FLDH + ((lane >> 4) << 3)) * 2);
    uint32_t aq[4][4];
    #pragma unroll
    for (int ks = 0; ks < 4; ks++)
        ldsm_x4(aq[ks][0], aq[ks][1], aq[ks][2], aq[ks][3], aQBase + ks * 32);

    // per-lane ldmatrix bases for K (non-trans B) and V (trans B)
    const uint32_t ksm = (uint32_t)__cvta_generic_to_shared(Ks);
    const uint32_t vsm = (uint32_t)__cvta_generic_to_shared(Vs);
    const uint32_t kFragBase = ksm +
        (uint32_t)((((lane & 7) + ((lane & 16) >> 1)) * FLDH + (lane & 8)) * 2);
    const int vm = lane >> 3;
    const uint32_t vFragBase = vsm +
        (uint32_t)((((vm & 1) * 8 + (lane & 7)) * FLDH + (vm >> 1) * 8) * 2);

    float m0 = -1e30f, m1 = -1e30f, l0 = 0.0f, l1 = 0.0f;
    float o[8][4];
    #pragma unroll
    for (int nf = 0; nf < 8; nf++)
        #pragma unroll
        for (int e = 0; e < 4; e++) o[nf][e] = 0.0f;

    for (int kt = 0; kt < T; kt++) {
        if (kt + 1 < T) stage(kt + 1, (kt + 1) & 1);
        cp_commit();
        cp_wait<1>();
        __syncthreads();

        const uint32_t kSt = kFragBase + (uint32_t)((kt & 1) * FT * 2);
        const uint32_t vSt = vFragBase + (uint32_t)((kt & 1) * FT * 2);
        const float* Msb = Ms + (kt & 1) * 64;

        // S = Q K^T : contraction over dk (4 k16 tiles), 8 key n-tiles
        float s[8][4];
        #pragma unroll
        for (int nf = 0; nf < 8; nf++)
            #pragma unroll
            for (int e = 0; e < 4; e++) s[nf][e] = 0.0f;

        #pragma unroll
        for (int ks = 0; ks < 4; ks++) {
            const uint32_t kOff = ks * 32;
            uint32_t bf[8][2];
            #pragma unroll
            for (int j = 0; j < 4; j++)
                ldsm_x4(bf[2*j][0], bf[2*j][1], bf[2*j+1][0], bf[2*j+1][1],
                        kSt + (uint32_t)(j * 16 * FLDH * 2) + kOff);
            #pragma unroll
            for (int nf = 0; nf < 8; nf++)
                mma_f16(s[nf], aq[ks][0], aq[ks][1], aq[ks][2], aq[ks][3],
                        bf[nf][0], bf[nf][1]);
        }

        // scale + mask + row max
        float rmax0 = -1e30f, rmax1 = -1e30f;
        #pragma unroll
        for (int nf = 0; nf < 8; nf++) {
            const float mk0 = Msb[nf * 8 + 2 * t];
            const float mk1 = Msb[nf * 8 + 2 * t + 1];
            s[nf][0] = s[nf][0] * SCALE + mk0;
            s[nf][1] = s[nf][1] * SCALE + mk1;
            s[nf][2] = s[nf][2] * SCALE + mk0;
            s[nf][3] = s[nf][3] * SCALE + mk1;
            rmax0 = fmaxf(rmax0, fmaxf(s[nf][0], s[nf][1]));
            rmax1 = fmaxf(rmax1, fmaxf(s[nf][2], s[nf][3]));
        }
        rmax0 = fmaxf(rmax0, __shfl_xor_sync(0xffffffffu, rmax0, 1));
        rmax0 = fmaxf(rmax0, __shfl_xor_sync(0xffffffffu, rmax0, 2));
        rmax1 = fmaxf(rmax1, __shfl_xor_sync(0xffffffffu, rmax1, 1));
        rmax1 = fmaxf(rmax1, __shfl_xor_sync(0xffffffffu, rmax1, 2));

        const float mn0 = fmaxf(m0, rmax0), mn1 = fmaxf(m1, rmax1);
        const float sc0 = __expf(m0 - mn0), sc1 = __expf(m1 - mn1);

        float rs0 = 0.0f, rs1 = 0.0f;
        #pragma unroll
        for (int nf = 0; nf < 8; nf++) {
            s[nf][0] = __expf(s[nf][0] - mn0);
            s[nf][1] = __expf(s[nf][1] - mn0);
            s[nf][2] = __expf(s[nf][2] - mn1);
            s[nf][3] = __expf(s[nf][3] - mn1);
            rs0 += s[nf][0] + s[nf][1];
            rs1 += s[nf][2] + s[nf][3];
        }
        rs0 += __shfl_xor_sync(0xffffffffu, rs0, 1);
        rs0 += __shfl_xor_sync(0xffffffffu, rs0, 2);
        rs1 += __shfl_xor_sync(0xffffffffu, rs1, 1);
        rs1 += __shfl_xor_sync(0xffffffffu, rs1, 2);

        l0 = l0 * sc0 + rs0;
        l1 = l1 * sc1 + rs1;
        m0 = mn0; m1 = mn1;

        #pragma unroll
        for (int nf = 0; nf < 8; nf++) {
            o[nf][0] *= sc0; o[nf][1] *= sc0;
            o[nf][2] *= sc1; o[nf][3] *= sc1;
        }

        // O += P V : P A-frags built directly from S C-frags (registers only)
        #pragma unroll
        for (int ks = 0; ks < 4; ks++) {
            const uint32_t a0 = packh2(s[2*ks][0],   s[2*ks][1]);
            const uint32_t a1 = packh2(s[2*ks][2],   s[2*ks][3]);
            const uint32_t a2 = packh2(s[2*ks+1][0], s[2*ks+1][1]);
            const uint32_t a3 = packh2(s[2*ks+1][2], s[2*ks+1][3]);
            uint32_t vf[8][2];
            #pragma unroll
            for (int j = 0; j < 4; j++)
                ldsm_x4_trans(vf[2*j][0], vf[2*j][1], vf[2*j+1][0], vf[2*j+1][1],
                              vSt + (uint32_t)((ks * 16 * FLDH + j * 16) * 2));
            #pragma unroll
            for (int nf = 0; nf < 8; nf++)
                mma_f16(o[nf], a0, a1, a2, a3, vf[nf][0], vf[nf][1]);
        }
        __syncthreads();
    }

    const float inv0 = 1.0f / l0, inv1 = 1.0f / l1;
    const int orow0 = b * Sn + qt * 64 + warp * 16 + g;
    #pragma unroll
    for (int nf = 0; nf < 8; nf++) {
        const int col = h * DKn + nf * 8 + 2 * t;
        *(__half2*)(&O[(size_t)orow0 * Dn + col]) =
            __float22half2_rn(make_float2(o[nf][0] * inv0, o[nf][1] * inv0));
        *(__half2*)(&O[(size_t)(orow0 + 8) * Dn + col]) =
            __float22half2_rn(make_float2(o[nf][2] * inv1, o[nf][3] * inv1));
    }
}

// ============================================================================
// LayerNorm over rows of 1024. One block (256 thr) per row, two-pass.
// ============================================================================
__global__ __launch_bounds__(256)
void layernorm_kernel(const float* __restrict__ in, const float* __restrict__ gamma,
                      const float* __restrict__ beta, float* __restrict__ out,
                      __half* __restrict__ hout)
{
    __shared__ float sb[9];
    const int row = blockIdx.x;
    const int tid = threadIdx.x;
    const float4 xv = *(const float4*)(in + (size_t)row * Dn + tid * 4);

    float ssum = xv.x + xv.y + xv.z + xv.w;
    #pragma unroll
    for (int off = 16; off; off >>= 1) ssum += __shfl_xor_sync(0xffffffffu, ssum, off);
    if ((tid & 31) == 0) sb[tid >> 5] = ssum;
    __syncthreads();
    if (tid == 0) {
        float s = 0.0f;
        #pragma unroll
        for (int i = 0; i < 8; i++) s += sb[i];
        sb[8] = s;
    }
    __syncthreads();
    const float mu = sb[8] * (1.0f / Dn);

    const float d0 = xv.x - mu, d1 = xv.y - mu, d2 = xv.z - mu, d3 = xv.w - mu;
    float sq = d0 * d0 + d1 * d1 + d2 * d2 + d3 * d3;
    __syncthreads();
    #pragma unroll
    for (int off = 16; off; off >>= 1) sq += __shfl_xor_sync(0xffffffffu, sq, off);
    if ((tid & 31) == 0) sb[tid >> 5] = sq;
    __syncthreads();
    if (tid == 0) {
        float s = 0.0f;
        #pragma unroll
        for (int i = 0; i < 8; i++) s += sb[i];
        sb[8] = s;
    }
    __syncthreads();
    const float inv = rsqrtf(sb[8] * (1.0f / Dn) + 1e-5f);

    const float4 gv = *(const float4*)(gamma + tid * 4);
    const float4 bv = *(const float4*)(beta + tid * 4);
    float4 ov;
    ov.x = d0 * inv * gv.x + bv.x;
    ov.y = d1 * inv * gv.y + bv.y;
    ov.z = d2 * inv * gv.z + bv.z;
    ov.w = d3 * inv * gv.w + bv.w;
    *(float4*)(out + (size_t)row * Dn + tid * 4) = ov;
    if (hout) {
        __half2 h0 = __float22half2_rn(make_float2(ov.x, ov.y));
        __half2 h1 = __float22half2_rn(make_float2(ov.z, ov.w));
        *(__half2*)(&hout[(size_t)row * Dn + tid * 4])     = h0;
        *(__half2*)(&hout[(size_t)row * Dn + tid * 4 + 2]) = h1;
    }
}

} // namespace enc

// ============================================================================
// kernel_launch
// ============================================================================
extern "C" void kernel_launch(void* const* d_in, const int* in_sizes, int n_in,
                              void* d_out, int out_size)
{
    using namespace enc;
    (void)in_sizes; (void)n_in; (void)out_size;

    const float* x    = (const float*)d_in[0];
    const float* mask = (const float*)d_in[1];
    const float* Wq   = (const float*)d_in[2];
    const float* bq   = (const float*)d_in[3];
    const float* Wk   = (const float*)d_in[4];
    const float* bk   = (const float*)d_in[5];
    const float* Wv   = (const float*)d_in[6];
    const float* bv   = (const float*)d_in[7];
    const float* Wo   = (const float*)d_in[8];
    const float* bo   = (const float*)d_in[9];
    const float* W1   = (const float*)d_in[10];
    const float* b1   = (const float*)d_in[11];
    const float* W2   = (const float*)d_in[12];
    const float* b2   = (const float*)d_in[13];
    const float* g1   = (const float*)d_in[14];
    const float* be1  = (const float*)d_in[15];
    const float* g2   = (const float*)d_in[16];
    const float* be2  = (const float*)d_in[17];
    float* out = (float*)d_out;

    float  *r, *x1;
    __half *qh, *kh, *vh, *oh, *x1h, *xh, *hh, *wq, *wk, *wv, *wo, *w1, *w2;
    cudaGetSymbolAddress((void**)&r,   g_r);
    cudaGetSymbolAddress((void**)&x1,  g_x1);
    cudaGetSymbolAddress((void**)&qh,  g_qh);
    cudaGetSymbolAddress((void**)&kh,  g_kh);
    cudaGetSymbolAddress((void**)&vh,  g_vh);
    cudaGetSymbolAddress((void**)&oh,  g_oh);
    cudaGetSymbolAddress((void**)&x1h, g_x1h);
    cudaGetSymbolAddress((void**)&xh,  g_xh);
    cudaGetSymbolAddress((void**)&hh,  g_hh);
    cudaGetSymbolAddress((void**)&wq,  g_wq);
    cudaGetSymbolAddress((void**)&wk,  g_wk);
    cudaGetSymbolAddress((void**)&wv,  g_wv);
    cudaGetSymbolAddress((void**)&wo,  g_wo);
    cudaGetSymbolAddress((void**)&w1,  g_w1);
    cudaGetSymbolAddress((void**)&w2,  g_w2);

    cudaFuncSetAttribute(gemm_qkv_kernel,
                         cudaFuncAttributeMaxDynamicSharedMemorySize, GEMM_SMEM);
    cudaFuncSetAttribute(gemm_kernel<false, true, true, false>,
                         cudaFuncAttributeMaxDynamicSharedMemorySize, GEMM_SMEM);
    cudaFuncSetAttribute(gemm_kernel<true, false, false, true>,
                         cudaFuncAttributeMaxDynamicSharedMemorySize, GEMM_SMEM);
    cudaFuncSetAttribute(flash_kernel,
                         cudaFuncAttributeMaxDynamicSharedMemorySize, FLASH_SMEM);

    // 0: one fused conversion launch (weights + x -> fp16)
    convert_all_kernel<<<(CN_TOTAL + 255) / 256, 256>>>(
        Wq, Wk, Wv, Wo, W1, W2, x, wq, wk, wv, wo, w1, w2, xh);

    const dim3 gQKV(24, 64);
    const dim3 gD(Dn / 128, Mn / 128);
    const dim3 gF(DFFn / 128, Mn / 128);

    // 1: fused QKV (fp16 outputs)
    gemm_qkv_kernel<<<gQKV, 256, GEMM_SMEM>>>(xh, wq, bq, wk, bk, wv, bv, qh, kh, vh);

    // 2: attention (fp16 MMA; output fp16)
    flash_kernel<<<dim3(Sn / 64, Hn, Bn), 128, FLASH_SMEM>>>(qh, kh, vh, mask, oh);

    // 3: O-proj + residual(x) -> r (f32)
    gemm_kernel<false, true, true, false><<<gD, 256, GEMM_SMEM>>>(
        oh, wo, bo, x, r, nullptr, Dn, Dn);

    // 4: LN1 -> x1 (f32) + x1h (fp16)
    layernorm_kernel<<<Mn, 256>>>(r, g1, be1, x1, x1h);

    // 5: FF1 (relu) -> hh (fp16)
    gemm_kernel<true, false, false, true><<<gF, 256, GEMM_SMEM>>>(
        x1h, w1, b1, nullptr, nullptr, hh, DFFn, Dn);

    // 6: FF2 + residual(x1) -> r (f32)
    gemm_kernel<false, true, true, false><<<gD, 256, GEMM_SMEM>>>(
        hh, w2, b2, x1, r, nullptr, Dn, DFFn);

    // 7: LN2 -> out
    layernorm_kernel<<<Mn, 256>>>(r, g2, be2, out, nullptr);
}